// round 7
// baseline (speedup 1.0000x reference)
#include <cuda_runtime.h>
#include <cuda_fp16.h>
#include <cstdint>

#define DEVI __device__ __forceinline__

// ---------------------------------------------------------------------------
// Scratch (device globals)
// ---------------------------------------------------------------------------
__device__ __half g_qh[33554432];   // [bs][blk i][c] canonical fp16
__device__ __half g_kh[33554432];   // [bs][blk j][c]
__device__ __half g_vth[33554432];  // [bs][c][blk j]  (pre-transposed)
__device__ float g_attn[33554432];  // aliased __half: attention out, packed A-frags
__device__ float g_xr[33554432];    // aliased __half: x packed A-frags
__device__ float g_wq[786432];      // aliased __half: W_qkv packed B-frags
__device__ float g_wp[262144];      // aliased __half: W_proj packed B-frags

DEVI uint32_t smem_u32(const void* p) {
    uint32_t a;
    asm("{ .reg .u64 t; cvta.to.shared.u64 t, %1; cvt.u32.u64 %0, t; }" : "=r"(a) : "l"(p));
    return a;
}
DEVI uint4 lds128(uint32_t a) {
    uint4 v;
    asm volatile("ld.shared.v4.u32 {%0,%1,%2,%3}, [%4];"
                 : "=r"(v.x), "=r"(v.y), "=r"(v.z), "=r"(v.w) : "r"(a));
    return v;
}
DEVI unsigned lds32(uint32_t a) {
    unsigned v;
    asm volatile("ld.shared.b32 %0, [%1];" : "=r"(v) : "r"(a));
    return v;
}
DEVI void cp16(uint32_t s, const void* g) {
    asm volatile("cp.async.cg.shared.global [%0], [%1], 16;" :: "r"(s), "l"(g));
}
DEVI void cp_commit() { asm volatile("cp.async.commit_group;"); }
template <int N> DEVI void cp_wait() { asm volatile("cp.async.wait_group %0;" :: "n"(N)); }

// fp16 mma m16n8k16, fp32 accum
DEVI void mma16(float* d, const uint4& a, unsigned b0, unsigned b1) {
    asm("mma.sync.aligned.m16n8k16.row.col.f32.f16.f16.f32 "
        "{%0,%1,%2,%3}, {%4,%5,%6,%7}, {%8,%9}, {%0,%1,%2,%3};"
        : "+f"(d[0]), "+f"(d[1]), "+f"(d[2]), "+f"(d[3])
        : "r"(a.x), "r"(a.y), "r"(a.z), "r"(a.w), "r"(b0), "r"(b1));
}

DEVI unsigned pack2(float lo, float hi) {
    __half2 h = __floats2half2_rn(lo, hi);
    return *(unsigned*)&h;
}

// ---------------------------------------------------------------------------
// fp16 fragment packs (R5-proven layouts)
// ---------------------------------------------------------------------------
__global__ void pack_x(const float* __restrict__ x, uint4* __restrict__ o) {
    int u = blockIdx.x * 256 + threadIdx.x;
    int l = u & 31, kk = (u >> 5) & 1, mf = (u >> 6) & 1, wm = (u >> 7) & 3;
    int kt = (u >> 9) & 15, mt = u >> 13;
    int r = mt * 128 + wm * 32 + mf * 16 + (l >> 2);
    int k = kt * 32 + kk * 16 + (l & 3) * 2;
    const float* p = x + (size_t)r * 512 + k;
    uint4 v;
    v.x = pack2(p[0], p[1]);
    v.y = pack2(p[8 * 512], p[8 * 512 + 1]);
    v.z = pack2(p[8], p[9]);
    v.w = pack2(p[8 * 512 + 8], p[8 * 512 + 9]);
    o[u] = v;
}

template <int NTOT>
__global__ void pack_w(const float* __restrict__ W, uint4* __restrict__ o) {
    int u = blockIdx.x * 256 + threadIdx.x;
    int l = u & 31, kk = (u >> 5) & 1, nfp = (u >> 6) & 3, wn = (u >> 8) & 1;
    int kt = (u >> 9) & 15, nt = u >> 13;
    int c = nt * 128 + wn * 64 + nfp * 16 + (l >> 2);
    int k = kt * 32 + kk * 16 + (l & 3) * 2;
    uint4 v;
    v.x = pack2(W[(size_t)k * NTOT + c], W[(size_t)(k + 1) * NTOT + c]);
    v.y = pack2(W[(size_t)(k + 8) * NTOT + c], W[(size_t)(k + 9) * NTOT + c]);
    v.z = pack2(W[(size_t)k * NTOT + c + 8], W[(size_t)(k + 1) * NTOT + c + 8]);
    v.w = pack2(W[(size_t)(k + 8) * NTOT + c + 8], W[(size_t)(k + 9) * NTOT + c + 8]);
    o[u] = v;
}

// Scatter one fp16 value into packed-A layout (attention epilogue -> proj input).
DEVI void store_attn_packed_h(int m, int c, float val) {
    int mt = m >> 7, rr = m & 127;
    int wm = rr >> 5, mf = (rr >> 4) & 1, e0 = (rr >> 3) & 1, g = rr & 7;
    int kt = c >> 5, ck = c & 31;
    int kk = (ck >> 4) & 1, e1 = (ck >> 3) & 1, t = (ck >> 1) & 3, par = ck & 1;
    size_t u = ((size_t)(mt * 16 + kt)) * 512 + wm * 128 + mf * 64 + kk * 32 + g * 4 + t;
    ((__half*)g_attn)[(u * 4 + e1 * 2 + e0) * 2 + par] = __float2half_rn(val);
}

// ---------------------------------------------------------------------------
// fp16 GEMM: CTA 128x128, warps 4(M)x2(N), 3-stage cp.async (R5-proven).
// EPI==0: qkv -> canonical fp16 Q/K + transposed fp16 V.  EPI==1: fp32 out.
// ---------------------------------------------------------------------------
template <int EPI>
__global__ void __launch_bounds__(256, 2) tc_gemm(
    const uint4* __restrict__ Apk, const uint4* __restrict__ Bpk,
    const float* __restrict__ bias, float* __restrict__ out)
{
    extern __shared__ unsigned char sm[];
    const uint32_t smb = smem_u32(sm);
    const int tid = threadIdx.x, lane = tid & 31, wid = tid >> 5;
    const int wm = wid & 3, wn = wid >> 2;
    const int nt = blockIdx.x, mt = blockIdx.y;

    const uint4* Ag = Apk + (size_t)mt * 8192;
    const uint4* Bg = Bpk + (size_t)nt * 8192;

    auto load_tile = [&](int kt, int s) {
        const uint32_t dst = smb + s * 16384;
        const uint4* sa = Ag + kt * 512;
        const uint4* sb = Bg + kt * 512;
        cp16(dst + tid * 16, sa + tid);
        cp16(dst + (tid + 256) * 16, sa + tid + 256);
        cp16(dst + 8192 + tid * 16, sb + tid);
        cp16(dst + 8192 + (tid + 256) * 16, sb + tid + 256);
        cp_commit();
    };

    float acc[2][8][4];
#pragma unroll
    for (int mf = 0; mf < 2; mf++)
#pragma unroll
        for (int nf = 0; nf < 8; nf++)
#pragma unroll
            for (int r = 0; r < 4; r++) acc[mf][nf][r] = 0.f;

    load_tile(0, 0);
    load_tile(1, 1);

    for (int kt = 0; kt < 16; kt++) {
        if (kt < 15) cp_wait<1>(); else cp_wait<0>();
        __syncthreads();
        if (kt + 2 < 16) load_tile(kt + 2, (kt + 2) % 3);

        const uint32_t st = smb + (kt % 3) * 16384;
        const uint32_t aB = st + (wm * 128 + lane) * 16;
        const uint32_t bB = st + 8192 + (wn * 256 + lane) * 16;
#pragma unroll
        for (int kk = 0; kk < 2; kk++) {
            uint4 a0 = lds128(aB + kk * 512);
            uint4 a1 = lds128(aB + 1024 + kk * 512);
            uint4 b0 = lds128(bB + kk * 512);
            uint4 b1 = lds128(bB + 1024 + kk * 512);
            uint4 b2 = lds128(bB + 2048 + kk * 512);
            uint4 b3 = lds128(bB + 3072 + kk * 512);
            mma16(acc[0][0], a0, b0.x, b0.y);
            mma16(acc[0][1], a0, b0.z, b0.w);
            mma16(acc[0][2], a0, b1.x, b1.y);
            mma16(acc[0][3], a0, b1.z, b1.w);
            mma16(acc[0][4], a0, b2.x, b2.y);
            mma16(acc[0][5], a0, b2.z, b2.w);
            mma16(acc[0][6], a0, b3.x, b3.y);
            mma16(acc[0][7], a0, b3.z, b3.w);
            mma16(acc[1][0], a1, b0.x, b0.y);
            mma16(acc[1][1], a1, b0.z, b0.w);
            mma16(acc[1][2], a1, b1.x, b1.y);
            mma16(acc[1][3], a1, b1.z, b1.w);
            mma16(acc[1][4], a1, b2.x, b2.y);
            mma16(acc[1][5], a1, b2.z, b2.w);
            mma16(acc[1][6], a1, b3.x, b3.y);
            mma16(acc[1][7], a1, b3.z, b3.w);
        }
    }

#pragma unroll
    for (int mf = 0; mf < 2; mf++)
#pragma unroll
        for (int nf = 0; nf < 8; nf++)
#pragma unroll
            for (int r = 0; r < 4; r++) {
                int row = mt * 128 + wm * 32 + mf * 16 + (lane >> 2) + ((r & 2) ? 8 : 0);
                int cc = nt * 128 + wn * 64 + nf * 8 + (lane & 3) * 2 + (r & 1);
                float v = acc[mf][nf][r] + bias[cc];
                if (EPI == 0) {
                    int b = row >> 13, n = row & 8191;
                    int blk = n >> 5, s = n & 31;
                    int bs = b * 32 + s;
                    int hh = cc / 192, rr = cc - hh * 192;
                    int kind = rr >> 6, c = hh * 64 + (rr & 63);
                    __half hv = __float2half_rn(v);
                    if (kind == 0)
                        g_qh[((size_t)(bs * 256 + blk)) * 512 + c] = hv;
                    else if (kind == 1)
                        g_kh[((size_t)(bs * 256 + blk)) * 512 + c] = hv;
                    else
                        g_vth[((size_t)(bs * 512 + c)) * 256 + blk] = hv;
                } else {
                    out[(size_t)row * 512 + cc] = v;
                }
            }
}

// ---------------------------------------------------------------------------
// Banded attention, all-fp16 mma. Grid (2,256). Warps 2(M) x 4(N).
// Smem rows padded to 40 halves (80B) -> conflict-free 4B fragment LDS.
// ---------------------------------------------------------------------------
template <int W>
__global__ void __launch_bounds__(256) attn_kernel()
{
    constexpr int NF = W / 32;            // phase1 n-frags per warp; phase2 jtiles
    constexpr int SSTF = W + 4;           // Ss stride (floats)
    constexpr int SSTH = W + 8;           // Ph stride (halves)
    constexpr int OFF_P = 64 * SSTF * 4;
    constexpr int OFF_T = OFF_P + 64 * SSTH * 2;
    constexpr int QS_SZ = 64 * 80;        // Q stage bytes
    constexpr int QK_ST = (64 + W) * 80;  // phase1 stage stride
    constexpr int V_ST = 256 * 80;        // phase2 stage stride

    extern __shared__ unsigned char smraw[];
    const uint32_t smb = smem_u32(smraw);
    float* Ss = (float*)smraw;

    const int tid = threadIdx.x, lane = tid & 31, wid = tid >> 5;
    const int g = lane >> 2, t = lane & 3;
    const int wm = wid & 1, wn = wid >> 1;
    const int bs = blockIdx.y;
    const int qt = (W == 128) ? (blockIdx.x ? 3 : 0) : (1 + blockIdx.x);
    const int i0 = qt * 64;
    const int jlo = (i0 >= 64) ? (i0 - 64) : 0;

    const __half* Qg = g_qh + (size_t)(bs * 256 + i0) * 512;
    const __half* Kg = g_kh + (size_t)(bs * 256 + jlo) * 512;
    const __half* Vg = g_vth + (size_t)bs * 512 * 256;

    // ---------------- phase 1: S = Q K^T ----------------
    auto ldqk = [&](int kt, int s) {
        const int k0 = kt * 32;
        const uint32_t qd = smb + OFF_T + s * QK_ST;
        const uint32_t kd = qd + QS_SZ;
        {
            int row = tid >> 2, hc = (tid & 3) * 8;
            cp16(qd + row * 80 + hc * 2, Qg + (size_t)row * 512 + k0 + hc);
        }
#pragma unroll
        for (int i = 0; i < W / 64; i++) {
            int u = tid + i * 256;
            int row = u >> 2, hc = (u & 3) * 8;
            cp16(kd + row * 80 + hc * 2, Kg + (size_t)row * 512 + k0 + hc);
        }
        cp_commit();
    };

    float acc[2][NF][4];
#pragma unroll
    for (int mf = 0; mf < 2; mf++)
#pragma unroll
        for (int nf = 0; nf < NF; nf++)
#pragma unroll
            for (int r = 0; r < 4; r++) acc[mf][nf][r] = 0.f;

    ldqk(0, 0);
    ldqk(1, 1);

    for (int kt = 0; kt < 16; kt++) {
        if (kt < 15) cp_wait<1>(); else cp_wait<0>();
        __syncthreads();
        if (kt + 2 < 16) ldqk(kt + 2, (kt + 2) % 3);

        const uint32_t qb = smb + OFF_T + (kt % 3) * QK_ST;
        const uint32_t kb = qb + QS_SZ;
#pragma unroll
        for (int kk = 0; kk < 2; kk++) {
            uint4 a[2];
#pragma unroll
            for (int mf = 0; mf < 2; mf++) {
                const uint32_t base = qb + (wm * 32 + mf * 16 + g) * 80 + kk * 32 + t * 4;
                a[mf].x = lds32(base);
                a[mf].y = lds32(base + 8 * 80);
                a[mf].z = lds32(base + 16);
                a[mf].w = lds32(base + 8 * 80 + 16);
            }
#pragma unroll
            for (int nf = 0; nf < NF; nf++) {
                const uint32_t bb = kb + (wn * (W / 4) + nf * 8 + g) * 80 + kk * 32 + t * 4;
                unsigned b0 = lds32(bb), b1 = lds32(bb + 16);
                mma16(acc[0][nf], a[0], b0, b1);
                mma16(acc[1][nf], a[1], b0, b1);
            }
        }
    }

    // scale + band mask + store S (fp32) to smem
#pragma unroll
    for (int mf = 0; mf < 2; mf++)
#pragma unroll
        for (int nf = 0; nf < NF; nf++)
#pragma unroll
            for (int r = 0; r < 4; r++) {
                int row = wm * 32 + mf * 16 + g + ((r & 2) ? 8 : 0);
                int jl = wn * (W / 4) + nf * 8 + t * 2 + (r & 1);
                int i = i0 + row, j = jlo + jl;
                float v = acc[mf][nf][r] * 0.125f;
                if (j < i - 64 || j > i + 64) v = -3.0e38f;
                Ss[row * SSTF + jl] = v;
            }
    __syncthreads();

    // fp32 softmax: 4 threads per row; write fp16 P
    {
        const int row = tid >> 2, part = tid & 3;
        float* rp = Ss + row * SSTF;
        __half* pp = (__half*)(smraw + OFF_P) + row * SSTH;
        float mx = -3.4e38f;
        for (int jl = part; jl < W; jl += 4) mx = fmaxf(mx, rp[jl]);
        mx = fmaxf(mx, __shfl_xor_sync(0xffffffffu, mx, 1));
        mx = fmaxf(mx, __shfl_xor_sync(0xffffffffu, mx, 2));
        float sm = 0.f;
        for (int jl = part; jl < W; jl += 4) {
            float e = __expf(rp[jl] - mx);
            rp[jl] = e;
            sm += e;
        }
        sm += __shfl_xor_sync(0xffffffffu, sm, 1);
        sm += __shfl_xor_sync(0xffffffffu, sm, 2);
        float inv = 1.0f / sm;
        for (int jl = part; jl < W; jl += 4) pp[jl] = __float2half_rn(rp[jl] * inv);
    }
    __syncthreads();

    // ---------------- phase 2: O = P V ----------------
    const int b = bs >> 5, s = bs & 31;

    for (int half = 0; half < 2; half++) {
        __syncthreads();   // Vs region free (prev half / phase1 readers done)

        auto ldv = [&](int jt, int st) {
            const uint32_t vd = smb + OFF_T + st * V_ST;
#pragma unroll
            for (int i = 0; i < 4; i++) {
                int u = tid + i * 256;
                int row = u >> 2, hc = (u & 3) * 8;
                cp16(vd + row * 80 + hc * 2,
                     Vg + (size_t)(half * 256 + row) * 256 + jlo + jt * 32 + hc);
            }
            cp_commit();
        };

        float acc2[2][8][4];
#pragma unroll
        for (int mf = 0; mf < 2; mf++)
#pragma unroll
            for (int nf = 0; nf < 8; nf++)
#pragma unroll
                for (int r = 0; r < 4; r++) acc2[mf][nf][r] = 0.f;

        ldv(0, 0);
        ldv(1, 1);

        for (int jt = 0; jt < NF; jt++) {
            if (jt < NF - 1) cp_wait<1>(); else cp_wait<0>();
            __syncthreads();
            if (jt + 2 < NF) ldv(jt + 2, (jt + 2) % 3);

            const uint32_t vb = smb + OFF_T + (jt % 3) * V_ST;
#pragma unroll
            for (int kk = 0; kk < 2; kk++) {
                uint4 a[2];
#pragma unroll
                for (int mf = 0; mf < 2; mf++) {
                    const uint32_t base = smb + OFF_P + (wm * 32 + mf * 16 + g) * (SSTH * 2) +
                                          jt * 64 + kk * 32 + t * 4;
                    a[mf].x = lds32(base);
                    a[mf].y = lds32(base + 8 * SSTH * 2);
                    a[mf].z = lds32(base + 16);
                    a[mf].w = lds32(base + 8 * SSTH * 2 + 16);
                }
#pragma unroll
                for (int nf = 0; nf < 8; nf++) {
                    const uint32_t bb = vb + (wn * 64 + nf * 8 + g) * 80 + kk * 32 + t * 4;
                    unsigned b0 = lds32(bb), b1 = lds32(bb + 16);
                    mma16(acc2[0][nf], a[0], b0, b1);
                    mma16(acc2[1][nf], a[1], b0, b1);
                }
            }
        }

#pragma unroll
        for (int mf = 0; mf < 2; mf++)
#pragma unroll
            for (int nf = 0; nf < 8; nf++)
#pragma unroll
                for (int r = 0; r < 4; r++) {
                    int row = wm * 32 + mf * 16 + g + ((r & 2) ? 8 : 0);
                    int c = half * 256 + wn * 64 + nf * 8 + t * 2 + (r & 1);
                    int m = b * 8192 + (i0 + row) * 32 + s;
                    store_attn_packed_h(m, c, acc2[mf][nf][r]);
                }
    }
}

// ---------------------------------------------------------------------------
extern "C" void kernel_launch(void* const* d_in, const int* in_sizes, int n_in,
                              void* d_out, int out_size)
{
    const float* x  = (const float*)d_in[0];
    const float* Wq = (const float*)d_in[1];
    const float* bq = (const float*)d_in[2];
    const float* Wp = (const float*)d_in[3];
    const float* bp = (const float*)d_in[4];
    float* out = (float*)d_out;

    void *pxr, *pwq, *pwp, *pattn;
    cudaGetSymbolAddress(&pxr, g_xr);
    cudaGetSymbolAddress(&pwq, g_wq);
    cudaGetSymbolAddress(&pwp, g_wp);
    cudaGetSymbolAddress(&pattn, g_attn);

    const int smG = 3 * 16384;        // 49152
    const int smA128 = 112640;        // Ss 33792 + Ph 17408 + tiles 61440
    const int smA192 = 137216;        // Ss 50176 + Ph 25600 + tiles 61440

    cudaFuncSetAttribute(tc_gemm<0>, cudaFuncAttributeMaxDynamicSharedMemorySize, smG);
    cudaFuncSetAttribute(tc_gemm<1>, cudaFuncAttributeMaxDynamicSharedMemorySize, smG);
    cudaFuncSetAttribute(attn_kernel<128>, cudaFuncAttributeMaxDynamicSharedMemorySize, smA128);
    cudaFuncSetAttribute(attn_kernel<192>, cudaFuncAttributeMaxDynamicSharedMemorySize, smA192);

    // 0) pack + fp16-round operands into m16n8k16 fragment order
    pack_x<<<16384, 256>>>(x, (uint4*)pxr);
    pack_w<1536><<<384, 256>>>(Wq, (uint4*)pwq);
    pack_w<512><<<128, 256>>>(Wp, (uint4*)pwp);

    // 1) QKV projection (fp16 mma) + canonical fp16 Q/K + transposed fp16 V
    tc_gemm<0><<<dim3(12, 512), 256, smG>>>((const uint4*)pxr, (const uint4*)pwq, bq, nullptr);

    // 2) banded attention (fp16 mma; writes fp16-packed g_attn)
    attn_kernel<128><<<dim3(2, 256), 256, smA128>>>();
    attn_kernel<192><<<dim3(2, 256), 256, smA192>>>();

    // 3) output projection (fp16 mma)
    tc_gemm<1><<<dim3(4, 512), 256, smG>>>((const uint4*)pattn, (const uint4*)pwp, bp, out);
}

// round 8
// speedup vs baseline: 1.4660x; 1.4660x over previous
#include <cuda_runtime.h>
#include <cuda_fp16.h>
#include <cstdint>

#define DEVI __device__ __forceinline__

// ---------------------------------------------------------------------------
// Scratch (device globals)
// ---------------------------------------------------------------------------
__device__ __half g_qh[33554432];   // [bs][blk][c] canonical fp16
__device__ __half g_kh[33554432];   // [bs][blk][c]
__device__ __half g_vh[33554432];   // [bs][blk][c]  (canonical; transpose via ldmatrix.trans)
__device__ float g_attn[33554432];  // aliased __half: attention out, packed A-frags
__device__ float g_xr[33554432];    // aliased __half: x packed A-frags
__device__ float g_wq[786432];      // aliased __half: W_qkv packed B-frags
__device__ float g_wp[262144];      // aliased __half: W_proj packed B-frags

DEVI uint32_t smem_u32(const void* p) {
    uint32_t a;
    asm("{ .reg .u64 t; cvta.to.shared.u64 t, %1; cvt.u32.u64 %0, t; }" : "=r"(a) : "l"(p));
    return a;
}
DEVI uint4 lds128(uint32_t a) {
    uint4 v;
    asm volatile("ld.shared.v4.u32 {%0,%1,%2,%3}, [%4];"
                 : "=r"(v.x), "=r"(v.y), "=r"(v.z), "=r"(v.w) : "r"(a));
    return v;
}
DEVI void ldsm4(uint4& r, uint32_t a) {
    asm volatile("ldmatrix.sync.aligned.m8n8.x4.shared.b16 {%0,%1,%2,%3}, [%4];"
                 : "=r"(r.x), "=r"(r.y), "=r"(r.z), "=r"(r.w) : "r"(a));
}
DEVI void ldsm4t(uint4& r, uint32_t a) {
    asm volatile("ldmatrix.sync.aligned.m8n8.x4.trans.shared.b16 {%0,%1,%2,%3}, [%4];"
                 : "=r"(r.x), "=r"(r.y), "=r"(r.z), "=r"(r.w) : "r"(a));
}
DEVI void cp16(uint32_t s, const void* g) {
    asm volatile("cp.async.cg.shared.global [%0], [%1], 16;" :: "r"(s), "l"(g));
}
DEVI void cp_commit() { asm volatile("cp.async.commit_group;"); }
template <int N> DEVI void cp_wait() { asm volatile("cp.async.wait_group %0;" :: "n"(N)); }

// fp16 mma m16n8k16, fp32 accum
DEVI void mma16(float* d, const uint4& a, unsigned b0, unsigned b1) {
    asm("mma.sync.aligned.m16n8k16.row.col.f32.f16.f16.f32 "
        "{%0,%1,%2,%3}, {%4,%5,%6,%7}, {%8,%9}, {%0,%1,%2,%3};"
        : "+f"(d[0]), "+f"(d[1]), "+f"(d[2]), "+f"(d[3])
        : "r"(a.x), "r"(a.y), "r"(a.z), "r"(a.w), "r"(b0), "r"(b1));
}

DEVI unsigned pack2(float lo, float hi) {
    __half2 h = __floats2half2_rn(lo, hi);
    return *(unsigned*)&h;
}

// ---------------------------------------------------------------------------
// fp16 fragment packs for the dense GEMMs (R5-proven layouts)
// ---------------------------------------------------------------------------
__global__ void pack_x(const float* __restrict__ x, uint4* __restrict__ o) {
    int u = blockIdx.x * 256 + threadIdx.x;
    int l = u & 31, kk = (u >> 5) & 1, mf = (u >> 6) & 1, wm = (u >> 7) & 3;
    int kt = (u >> 9) & 15, mt = u >> 13;
    int r = mt * 128 + wm * 32 + mf * 16 + (l >> 2);
    int k = kt * 32 + kk * 16 + (l & 3) * 2;
    const float* p = x + (size_t)r * 512 + k;
    uint4 v;
    v.x = pack2(p[0], p[1]);
    v.y = pack2(p[8 * 512], p[8 * 512 + 1]);
    v.z = pack2(p[8], p[9]);
    v.w = pack2(p[8 * 512 + 8], p[8 * 512 + 9]);
    o[u] = v;
}

template <int NTOT>
__global__ void pack_w(const float* __restrict__ W, uint4* __restrict__ o) {
    int u = blockIdx.x * 256 + threadIdx.x;
    int l = u & 31, kk = (u >> 5) & 1, nfp = (u >> 6) & 3, wn = (u >> 8) & 1;
    int kt = (u >> 9) & 15, nt = u >> 13;
    int c = nt * 128 + wn * 64 + nfp * 16 + (l >> 2);
    int k = kt * 32 + kk * 16 + (l & 3) * 2;
    uint4 v;
    v.x = pack2(W[(size_t)k * NTOT + c], W[(size_t)(k + 1) * NTOT + c]);
    v.y = pack2(W[(size_t)(k + 8) * NTOT + c], W[(size_t)(k + 9) * NTOT + c]);
    v.z = pack2(W[(size_t)k * NTOT + c + 8], W[(size_t)(k + 1) * NTOT + c + 8]);
    v.w = pack2(W[(size_t)(k + 8) * NTOT + c + 8], W[(size_t)(k + 9) * NTOT + c + 8]);
    o[u] = v;
}

// Scatter one fp16 value into packed-A layout (attention epilogue -> proj input).
DEVI void store_attn_packed_h(int m, int c, float val) {
    int mt = m >> 7, rr = m & 127;
    int wm = rr >> 5, mf = (rr >> 4) & 1, e0 = (rr >> 3) & 1, g = rr & 7;
    int kt = c >> 5, ck = c & 31;
    int kk = (ck >> 4) & 1, e1 = (ck >> 3) & 1, t = (ck >> 1) & 3, par = ck & 1;
    size_t u = ((size_t)(mt * 16 + kt)) * 512 + wm * 128 + mf * 64 + kk * 32 + g * 4 + t;
    ((__half*)g_attn)[(u * 4 + e1 * 2 + e0) * 2 + par] = __float2half_rn(val);
}

// ---------------------------------------------------------------------------
// fp16 GEMM: CTA 128x128, warps 4(M)x2(N), 3-stage cp.async (R5-proven loop).
// EPI==0: qkv -> canonical fp16 Q/K/V via paired half2 stores.  EPI==1: fp32 out.
// ---------------------------------------------------------------------------
template <int EPI>
__global__ void __launch_bounds__(256, 2) tc_gemm(
    const uint4* __restrict__ Apk, const uint4* __restrict__ Bpk,
    const float* __restrict__ bias, float* __restrict__ out)
{
    extern __shared__ unsigned char sm[];
    const uint32_t smb = smem_u32(sm);
    const int tid = threadIdx.x, lane = tid & 31, wid = tid >> 5;
    const int wm = wid & 3, wn = wid >> 2;
    const int nt = blockIdx.x, mt = blockIdx.y;

    const uint4* Ag = Apk + (size_t)mt * 8192;
    const uint4* Bg = Bpk + (size_t)nt * 8192;

    auto load_tile = [&](int kt, int s) {
        const uint32_t dst = smb + s * 16384;
        const uint4* sa = Ag + kt * 512;
        const uint4* sb = Bg + kt * 512;
        cp16(dst + tid * 16, sa + tid);
        cp16(dst + (tid + 256) * 16, sa + tid + 256);
        cp16(dst + 8192 + tid * 16, sb + tid);
        cp16(dst + 8192 + (tid + 256) * 16, sb + tid + 256);
        cp_commit();
    };

    float acc[2][8][4];
#pragma unroll
    for (int mf = 0; mf < 2; mf++)
#pragma unroll
        for (int nf = 0; nf < 8; nf++)
#pragma unroll
            for (int r = 0; r < 4; r++) acc[mf][nf][r] = 0.f;

    load_tile(0, 0);
    load_tile(1, 1);

    for (int kt = 0; kt < 16; kt++) {
        if (kt < 15) cp_wait<1>(); else cp_wait<0>();
        __syncthreads();
        if (kt + 2 < 16) load_tile(kt + 2, (kt + 2) % 3);

        const uint32_t st = smb + (kt % 3) * 16384;
        const uint32_t aB = st + (wm * 128 + lane) * 16;
        const uint32_t bB = st + 8192 + (wn * 256 + lane) * 16;
#pragma unroll
        for (int kk = 0; kk < 2; kk++) {
            uint4 a0 = lds128(aB + kk * 512);
            uint4 a1 = lds128(aB + 1024 + kk * 512);
            uint4 b0 = lds128(bB + kk * 512);
            uint4 b1 = lds128(bB + 1024 + kk * 512);
            uint4 b2 = lds128(bB + 2048 + kk * 512);
            uint4 b3 = lds128(bB + 3072 + kk * 512);
            mma16(acc[0][0], a0, b0.x, b0.y);
            mma16(acc[0][1], a0, b0.z, b0.w);
            mma16(acc[0][2], a0, b1.x, b1.y);
            mma16(acc[0][3], a0, b1.z, b1.w);
            mma16(acc[0][4], a0, b2.x, b2.y);
            mma16(acc[0][5], a0, b2.z, b2.w);
            mma16(acc[0][6], a0, b3.x, b3.y);
            mma16(acc[0][7], a0, b3.z, b3.w);
            mma16(acc[1][0], a1, b0.x, b0.y);
            mma16(acc[1][1], a1, b0.z, b0.w);
            mma16(acc[1][2], a1, b1.x, b1.y);
            mma16(acc[1][3], a1, b1.z, b1.w);
            mma16(acc[1][4], a1, b2.x, b2.y);
            mma16(acc[1][5], a1, b2.z, b2.w);
            mma16(acc[1][6], a1, b3.x, b3.y);
            mma16(acc[1][7], a1, b3.z, b3.w);
        }
    }

#pragma unroll
    for (int mf = 0; mf < 2; mf++)
#pragma unroll
        for (int nf = 0; nf < 8; nf++)
#pragma unroll
            for (int rp = 0; rp < 2; rp++) {
                int row = mt * 128 + wm * 32 + mf * 16 + (lane >> 2) + rp * 8;
                int cc = nt * 128 + wn * 64 + nf * 8 + (lane & 3) * 2;
                float v0 = acc[mf][nf][rp * 2] + bias[cc];
                float v1 = acc[mf][nf][rp * 2 + 1] + bias[cc + 1];
                if (EPI == 0) {
                    int b = row >> 13, n = row & 8191;
                    int blk = n >> 5, s = n & 31;
                    int bs = b * 32 + s;
                    int hh = cc / 192, rr = cc - hh * 192;
                    int kind = rr >> 6, c = hh * 64 + (rr & 63);
                    __half2 hv = __floats2half2_rn(v0, v1);
                    __half* dp = (kind == 0) ? g_qh : (kind == 1) ? g_kh : g_vh;
                    *(__half2*)(dp + ((size_t)(bs * 256 + blk)) * 512 + c) = hv;
                } else {
                    float* db = out + (size_t)row * 512 + cc;
                    db[0] = v0;
                    db[1] = v1;
                }
            }
}

// ---------------------------------------------------------------------------
// Banded attention, fp16 mma + ldmatrix frag loads. Grid (2,256). Warps 2x4.
// Phase-1 tiles: 80B rows (conflict-free). Phase-2 V tiles: canonical [j][c],
// B frags formed by ldmatrix.trans (smem crossbar does the transpose).
// ---------------------------------------------------------------------------
template <int W>
__global__ void __launch_bounds__(256) attn_kernel()
{
    constexpr int NF = W / 32;            // phase1 n-frags per warp; phase2 jtiles
    constexpr int SSTF = W + 4;           // Ss stride (floats)
    constexpr int SSTH = W + 8;           // Ph stride (halves)
    constexpr int OFF_P = 64 * SSTF * 4;
    constexpr int OFF_T = OFF_P + 64 * SSTH * 2;
    constexpr int QS_SZ = 64 * 80;        // Q stage bytes
    constexpr int QK_ST = (64 + W) * 80;  // phase1 stage stride
    constexpr int V_ST = 32 * 528;        // phase2 stage stride (32 j x 264 halves)

    extern __shared__ unsigned char smraw[];
    const uint32_t smb = smem_u32(smraw);
    float* Ss = (float*)smraw;

    const int tid = threadIdx.x, lane = tid & 31, wid = tid >> 5;
    const int g = lane >> 2, t = lane & 3;
    const int wm = wid & 1, wn = wid >> 1;
    const int bs = blockIdx.y;
    const int qt = (W == 128) ? (blockIdx.x ? 3 : 0) : (1 + blockIdx.x);
    const int i0 = qt * 64;
    const int jlo = (i0 >= 64) ? (i0 - 64) : 0;

    const __half* Qg = g_qh + (size_t)(bs * 256 + i0) * 512;
    const __half* Kg = g_kh + (size_t)(bs * 256 + jlo) * 512;
    const __half* Vg = g_vh + (size_t)(bs * 256 + jlo) * 512;

    // ---------------- phase 1: S = Q K^T ----------------
    auto ldqk = [&](int kt, int s) {
        const int k0 = kt * 32;
        const uint32_t qd = smb + OFF_T + s * QK_ST;
        const uint32_t kd = qd + QS_SZ;
        {
            int row = tid >> 2, hc = (tid & 3) * 8;
            cp16(qd + row * 80 + hc * 2, Qg + (size_t)row * 512 + k0 + hc);
        }
#pragma unroll
        for (int i = 0; i < W / 64; i++) {
            int u = tid + i * 256;
            int row = u >> 2, hc = (u & 3) * 8;
            cp16(kd + row * 80 + hc * 2, Kg + (size_t)row * 512 + k0 + hc);
        }
        cp_commit();
    };

    float acc[2][NF][4];
#pragma unroll
    for (int mf = 0; mf < 2; mf++)
#pragma unroll
        for (int nf = 0; nf < NF; nf++)
#pragma unroll
            for (int r = 0; r < 4; r++) acc[mf][nf][r] = 0.f;

    ldqk(0, 0);
    ldqk(1, 1);

    for (int kt = 0; kt < 16; kt++) {
        if (kt < 15) cp_wait<1>(); else cp_wait<0>();
        __syncthreads();
        if (kt + 2 < 16) ldqk(kt + 2, (kt + 2) % 3);

        const uint32_t qb = smb + OFF_T + (kt % 3) * QK_ST;
        const uint32_t kb = qb + QS_SZ;
#pragma unroll
        for (int kk = 0; kk < 2; kk++) {
            uint4 a[2];
#pragma unroll
            for (int mf = 0; mf < 2; mf++)
                ldsm4(a[mf], qb + (wm * 32 + mf * 16 + (lane & 15)) * 80 +
                              kk * 32 + (lane >> 4) * 16);
#pragma unroll
            for (int np = 0; np < NF / 2; np++) {
                uint4 bm;
                ldsm4(bm, kb + (wn * (W / 4) + (np * 2 + (lane >> 4)) * 8 + (lane & 7)) * 80 +
                           kk * 32 + ((lane >> 3) & 1) * 16);
                mma16(acc[0][np * 2], a[0], bm.x, bm.y);
                mma16(acc[1][np * 2], a[1], bm.x, bm.y);
                mma16(acc[0][np * 2 + 1], a[0], bm.z, bm.w);
                mma16(acc[1][np * 2 + 1], a[1], bm.z, bm.w);
            }
        }
    }

    // scale + band mask + store S (fp32) to smem
#pragma unroll
    for (int mf = 0; mf < 2; mf++)
#pragma unroll
        for (int nf = 0; nf < NF; nf++)
#pragma unroll
            for (int r = 0; r < 4; r++) {
                int row = wm * 32 + mf * 16 + g + ((r & 2) ? 8 : 0);
                int jl = wn * (W / 4) + nf * 8 + t * 2 + (r & 1);
                int i = i0 + row, j = jlo + jl;
                float v = acc[mf][nf][r] * 0.125f;
                if (j < i - 64 || j > i + 64) v = -3.0e38f;
                Ss[row * SSTF + jl] = v;
            }
    __syncthreads();

    // fp32 softmax: 4 threads per row; write fp16 P
    {
        const int row = tid >> 2, part = tid & 3;
        float* rp = Ss + row * SSTF;
        __half* pp = (__half*)(smraw + OFF_P) + row * SSTH;
        float mx = -3.4e38f;
        for (int jl = part; jl < W; jl += 4) mx = fmaxf(mx, rp[jl]);
        mx = fmaxf(mx, __shfl_xor_sync(0xffffffffu, mx, 1));
        mx = fmaxf(mx, __shfl_xor_sync(0xffffffffu, mx, 2));
        float sm = 0.f;
        for (int jl = part; jl < W; jl += 4) {
            float e = __expf(rp[jl] - mx);
            rp[jl] = e;
            sm += e;
        }
        sm += __shfl_xor_sync(0xffffffffu, sm, 1);
        sm += __shfl_xor_sync(0xffffffffu, sm, 2);
        float inv = 1.0f / sm;
        for (int jl = part; jl < W; jl += 4) pp[jl] = __float2half_rn(rp[jl] * inv);
    }
    __syncthreads();

    // ---------------- phase 2: O = P V ----------------
    const int b = bs >> 5, s = bs & 31;

    for (int half = 0; half < 2; half++) {
        __syncthreads();   // tile region free (phase1 / prev half readers done)

        auto ldv = [&](int jt, int st) {
            const uint32_t vd = smb + OFF_T + st * V_ST;
#pragma unroll
            for (int i = 0; i < 4; i++) {
                int u = tid + i * 256;
                int row = u >> 5, ch = u & 31;
                cp16(vd + row * 528 + ch * 16,
                     Vg + (size_t)(jt * 32 + row) * 512 + half * 256 + ch * 8);
            }
            cp_commit();
        };

        float acc2[2][8][4];
#pragma unroll
        for (int mf = 0; mf < 2; mf++)
#pragma unroll
            for (int nf = 0; nf < 8; nf++)
#pragma unroll
                for (int r = 0; r < 4; r++) acc2[mf][nf][r] = 0.f;

        ldv(0, 0);
        ldv(1, 1);

        for (int jt = 0; jt < NF; jt++) {
            if (jt < NF - 1) cp_wait<1>(); else cp_wait<0>();
            __syncthreads();
            if (jt + 2 < NF) ldv(jt + 2, (jt + 2) % 3);

            const uint32_t vb = smb + OFF_T + (jt % 3) * V_ST;
#pragma unroll
            for (int kk = 0; kk < 2; kk++) {
                uint4 a[2];
#pragma unroll
                for (int mf = 0; mf < 2; mf++)
                    ldsm4(a[mf], smb + OFF_P + (wm * 32 + mf * 16 + (lane & 15)) * (SSTH * 2) +
                                  (jt * 32 + kk * 16 + (lane >> 4) * 8) * 2);
#pragma unroll
                for (int np = 0; np < 4; np++) {
                    uint4 bm;
                    ldsm4t(bm, vb + (kk * 16 + ((lane >> 3) & 1) * 8 + (lane & 7)) * 528 +
                                (wn * 64 + (np * 2 + (lane >> 4)) * 8) * 2);
                    mma16(acc2[0][np * 2], a[0], bm.x, bm.y);
                    mma16(acc2[1][np * 2], a[1], bm.x, bm.y);
                    mma16(acc2[0][np * 2 + 1], a[0], bm.z, bm.w);
                    mma16(acc2[1][np * 2 + 1], a[1], bm.z, bm.w);
                }
            }
        }

#pragma unroll
        for (int mf = 0; mf < 2; mf++)
#pragma unroll
            for (int nf = 0; nf < 8; nf++)
#pragma unroll
                for (int r = 0; r < 4; r++) {
                    int row = wm * 32 + mf * 16 + g + ((r & 2) ? 8 : 0);
                    int c = half * 256 + wn * 64 + nf * 8 + t * 2 + (r & 1);
                    int m = b * 8192 + (i0 + row) * 32 + s;
                    store_attn_packed_h(m, c, acc2[mf][nf][r]);
                }
    }
}

// ---------------------------------------------------------------------------
extern "C" void kernel_launch(void* const* d_in, const int* in_sizes, int n_in,
                              void* d_out, int out_size)
{
    const float* x  = (const float*)d_in[0];
    const float* Wq = (const float*)d_in[1];
    const float* bq = (const float*)d_in[2];
    const float* Wp = (const float*)d_in[3];
    const float* bp = (const float*)d_in[4];
    float* out = (float*)d_out;

    void *pxr, *pwq, *pwp, *pattn;
    cudaGetSymbolAddress(&pxr, g_xr);
    cudaGetSymbolAddress(&pwq, g_wq);
    cudaGetSymbolAddress(&pwp, g_wp);
    cudaGetSymbolAddress(&pattn, g_attn);

    const int smG = 3 * 16384;        // 49152
    const int smA128 = 101888;        // Ss 33792 + Ph 17408 + tiles 50688
    const int smA192 = 137216;        // Ss 50176 + Ph 25600 + tiles 61440

    cudaFuncSetAttribute(tc_gemm<0>, cudaFuncAttributeMaxDynamicSharedMemorySize, smG);
    cudaFuncSetAttribute(tc_gemm<1>, cudaFuncAttributeMaxDynamicSharedMemorySize, smG);
    cudaFuncSetAttribute(attn_kernel<128>, cudaFuncAttributeMaxDynamicSharedMemorySize, smA128);
    cudaFuncSetAttribute(attn_kernel<192>, cudaFuncAttributeMaxDynamicSharedMemorySize, smA192);

    // 0) pack + fp16-round operands into m16n8k16 fragment order
    pack_x<<<16384, 256>>>(x, (uint4*)pxr);
    pack_w<1536><<<384, 256>>>(Wq, (uint4*)pwq);
    pack_w<512><<<128, 256>>>(Wp, (uint4*)pwp);

    // 1) QKV projection (fp16 mma) -> canonical fp16 Q/K/V (half2 stores)
    tc_gemm<0><<<dim3(12, 512), 256, smG>>>((const uint4*)pxr, (const uint4*)pwq, bq, nullptr);

    // 2) banded attention (fp16 mma + ldmatrix; writes fp16-packed g_attn)
    attn_kernel<128><<<dim3(2, 256), 256, smA128>>>();
    attn_kernel<192><<<dim3(2, 256), 256, smA192>>>();

    // 3) output projection (fp16 mma)
    tc_gemm<1><<<dim3(4, 512), 256, smG>>>((const uint4*)pattn, (const uint4*)pwp, bp, out);
}

// round 9
// speedup vs baseline: 1.6267x; 1.1096x over previous
#include <cuda_runtime.h>
#include <cuda_fp16.h>
#include <cstdint>

#define DEVI __device__ __forceinline__

// ---------------------------------------------------------------------------
// Scratch (device globals)
// ---------------------------------------------------------------------------
__device__ __half g_qh[33554432];   // [bs][blk][c] canonical fp16
__device__ __half g_kh[33554432];   // [bs][blk][c]
__device__ __half g_vh[33554432];   // [bs][blk][c]  (canonical; transpose via ldmatrix.trans)
__device__ float g_attn[33554432];  // aliased __half: attention out, packed A-frags
__device__ float g_xr[33554432];    // aliased __half: x packed A-frags
__device__ float g_wq[786432];      // aliased __half: W_qkv packed B-frags
__device__ float g_wp[262144];      // aliased __half: W_proj packed B-frags

DEVI uint32_t smem_u32(const void* p) {
    uint32_t a;
    asm("{ .reg .u64 t; cvta.to.shared.u64 t, %1; cvt.u32.u64 %0, t; }" : "=r"(a) : "l"(p));
    return a;
}
DEVI uint4 lds128(uint32_t a) {
    uint4 v;
    asm volatile("ld.shared.v4.u32 {%0,%1,%2,%3}, [%4];"
                 : "=r"(v.x), "=r"(v.y), "=r"(v.z), "=r"(v.w) : "r"(a));
    return v;
}
DEVI void ldsm4(uint4& r, uint32_t a) {
    asm volatile("ldmatrix.sync.aligned.m8n8.x4.shared.b16 {%0,%1,%2,%3}, [%4];"
                 : "=r"(r.x), "=r"(r.y), "=r"(r.z), "=r"(r.w) : "r"(a));
}
DEVI void ldsm4t(uint4& r, uint32_t a) {
    asm volatile("ldmatrix.sync.aligned.m8n8.x4.trans.shared.b16 {%0,%1,%2,%3}, [%4];"
                 : "=r"(r.x), "=r"(r.y), "=r"(r.z), "=r"(r.w) : "r"(a));
}
DEVI void cp16(uint32_t s, const void* g) {
    asm volatile("cp.async.cg.shared.global [%0], [%1], 16;" :: "r"(s), "l"(g));
}
DEVI void cp_commit() { asm volatile("cp.async.commit_group;"); }
template <int N> DEVI void cp_wait() { asm volatile("cp.async.wait_group %0;" :: "n"(N)); }

// fp16 mma m16n8k16, fp32 accum
DEVI void mma16(float* d, const uint4& a, unsigned b0, unsigned b1) {
    asm("mma.sync.aligned.m16n8k16.row.col.f32.f16.f16.f32 "
        "{%0,%1,%2,%3}, {%4,%5,%6,%7}, {%8,%9}, {%0,%1,%2,%3};"
        : "+f"(d[0]), "+f"(d[1]), "+f"(d[2]), "+f"(d[3])
        : "r"(a.x), "r"(a.y), "r"(a.z), "r"(a.w), "r"(b0), "r"(b1));
}

DEVI unsigned pack2(float lo, float hi) {
    __half2 h = __floats2half2_rn(lo, hi);
    return *(unsigned*)&h;
}

// ---------------------------------------------------------------------------
// fp16 fragment packs for the dense GEMMs (R5-proven layouts)
// ---------------------------------------------------------------------------
__global__ void pack_x(const float* __restrict__ x, uint4* __restrict__ o) {
    int u = blockIdx.x * 256 + threadIdx.x;
    int l = u & 31, kk = (u >> 5) & 1, mf = (u >> 6) & 1, wm = (u >> 7) & 3;
    int kt = (u >> 9) & 15, mt = u >> 13;
    int r = mt * 128 + wm * 32 + mf * 16 + (l >> 2);
    int k = kt * 32 + kk * 16 + (l & 3) * 2;
    const float* p = x + (size_t)r * 512 + k;
    uint4 v;
    v.x = pack2(p[0], p[1]);
    v.y = pack2(p[8 * 512], p[8 * 512 + 1]);
    v.z = pack2(p[8], p[9]);
    v.w = pack2(p[8 * 512 + 8], p[8 * 512 + 9]);
    o[u] = v;
}

template <int NTOT>
__global__ void pack_w(const float* __restrict__ W, uint4* __restrict__ o) {
    int u = blockIdx.x * 256 + threadIdx.x;
    int l = u & 31, kk = (u >> 5) & 1, nfp = (u >> 6) & 3, wn = (u >> 8) & 1;
    int kt = (u >> 9) & 15, nt = u >> 13;
    int c = nt * 128 + wn * 64 + nfp * 16 + (l >> 2);
    int k = kt * 32 + kk * 16 + (l & 3) * 2;
    uint4 v;
    v.x = pack2(W[(size_t)k * NTOT + c], W[(size_t)(k + 1) * NTOT + c]);
    v.y = pack2(W[(size_t)(k + 8) * NTOT + c], W[(size_t)(k + 9) * NTOT + c]);
    v.z = pack2(W[(size_t)k * NTOT + c + 8], W[(size_t)(k + 1) * NTOT + c + 8]);
    v.w = pack2(W[(size_t)(k + 8) * NTOT + c + 8], W[(size_t)(k + 9) * NTOT + c + 8]);
    o[u] = v;
}

// Scatter an adjacent-c pair into packed-A layout as one half2 store.
DEVI void store_attn_packed_h2(int m, int c, float v0, float v1) {
    int mt = m >> 7, rr = m & 127;
    int wm = rr >> 5, mf = (rr >> 4) & 1, e0 = (rr >> 3) & 1, g = rr & 7;
    int kt = c >> 5, ck = c & 31;
    int kk = (ck >> 4) & 1, e1 = (ck >> 3) & 1, t = (ck >> 1) & 3;
    size_t u = ((size_t)(mt * 16 + kt)) * 512 + wm * 128 + mf * 64 + kk * 32 + g * 4 + t;
    *(__half2*)((__half*)g_attn + (u * 4 + e1 * 2 + e0) * 2) = __floats2half2_rn(v0, v1);
}

// ---------------------------------------------------------------------------
// fp16 GEMM: CTA 128x128, warps 4(M)x2(N), 4-stage cp.async.
// EPI==0: qkv -> canonical fp16 Q/K/V via paired half2 stores.  EPI==1: fp32 out.
// ---------------------------------------------------------------------------
template <int EPI>
__global__ void __launch_bounds__(256, 2) tc_gemm(
    const uint4* __restrict__ Apk, const uint4* __restrict__ Bpk,
    const float* __restrict__ bias, float* __restrict__ out)
{
    extern __shared__ unsigned char sm[];
    const uint32_t smb = smem_u32(sm);
    const int tid = threadIdx.x, lane = tid & 31, wid = tid >> 5;
    const int wm = wid & 3, wn = wid >> 2;
    const int nt = blockIdx.x, mt = blockIdx.y;

    const uint4* Ag = Apk + (size_t)mt * 8192;
    const uint4* Bg = Bpk + (size_t)nt * 8192;

    auto load_tile = [&](int kt, int s) {
        const uint32_t dst = smb + s * 16384;
        const uint4* sa = Ag + kt * 512;
        const uint4* sb = Bg + kt * 512;
        cp16(dst + tid * 16, sa + tid);
        cp16(dst + (tid + 256) * 16, sa + tid + 256);
        cp16(dst + 8192 + tid * 16, sb + tid);
        cp16(dst + 8192 + (tid + 256) * 16, sb + tid + 256);
        cp_commit();
    };

    float acc[2][8][4];
#pragma unroll
    for (int mf = 0; mf < 2; mf++)
#pragma unroll
        for (int nf = 0; nf < 8; nf++)
#pragma unroll
            for (int r = 0; r < 4; r++) acc[mf][nf][r] = 0.f;

    load_tile(0, 0);
    load_tile(1, 1);
    load_tile(2, 2);

    for (int kt = 0; kt < 16; kt++) {
        if (kt < 14) cp_wait<2>();
        else if (kt == 14) cp_wait<1>();
        else cp_wait<0>();
        __syncthreads();
        if (kt + 3 < 16) load_tile(kt + 3, (kt + 3) & 3);

        const uint32_t st = smb + (kt & 3) * 16384;
        const uint32_t aB = st + (wm * 128 + lane) * 16;
        const uint32_t bB = st + 8192 + (wn * 256 + lane) * 16;
#pragma unroll
        for (int kk = 0; kk < 2; kk++) {
            uint4 a0 = lds128(aB + kk * 512);
            uint4 a1 = lds128(aB + 1024 + kk * 512);
            uint4 b0 = lds128(bB + kk * 512);
            uint4 b1 = lds128(bB + 1024 + kk * 512);
            uint4 b2 = lds128(bB + 2048 + kk * 512);
            uint4 b3 = lds128(bB + 3072 + kk * 512);
            mma16(acc[0][0], a0, b0.x, b0.y);
            mma16(acc[0][1], a0, b0.z, b0.w);
            mma16(acc[0][2], a0, b1.x, b1.y);
            mma16(acc[0][3], a0, b1.z, b1.w);
            mma16(acc[0][4], a0, b2.x, b2.y);
            mma16(acc[0][5], a0, b2.z, b2.w);
            mma16(acc[0][6], a0, b3.x, b3.y);
            mma16(acc[0][7], a0, b3.z, b3.w);
            mma16(acc[1][0], a1, b0.x, b0.y);
            mma16(acc[1][1], a1, b0.z, b0.w);
            mma16(acc[1][2], a1, b1.x, b1.y);
            mma16(acc[1][3], a1, b1.z, b1.w);
            mma16(acc[1][4], a1, b2.x, b2.y);
            mma16(acc[1][5], a1, b2.z, b2.w);
            mma16(acc[1][6], a1, b3.x, b3.y);
            mma16(acc[1][7], a1, b3.z, b3.w);
        }
    }

#pragma unroll
    for (int mf = 0; mf < 2; mf++)
#pragma unroll
        for (int nf = 0; nf < 8; nf++)
#pragma unroll
            for (int rp = 0; rp < 2; rp++) {
                int row = mt * 128 + wm * 32 + mf * 16 + (lane >> 2) + rp * 8;
                int cc = nt * 128 + wn * 64 + nf * 8 + (lane & 3) * 2;
                float v0 = acc[mf][nf][rp * 2] + bias[cc];
                float v1 = acc[mf][nf][rp * 2 + 1] + bias[cc + 1];
                if (EPI == 0) {
                    int b = row >> 13, n = row & 8191;
                    int blk = n >> 5, s = n & 31;
                    int bs = b * 32 + s;
                    int hh = cc / 192, rr = cc - hh * 192;
                    int kind = rr >> 6, c = hh * 64 + (rr & 63);
                    __half2 hv = __floats2half2_rn(v0, v1);
                    __half* dp = (kind == 0) ? g_qh : (kind == 1) ? g_kh : g_vh;
                    *(__half2*)(dp + ((size_t)(bs * 256 + blk)) * 512 + c) = hv;
                } else {
                    float* db = out + (size_t)row * 512 + cc;
                    db[0] = v0;
                    db[1] = v1;
                }
            }
}

// ---------------------------------------------------------------------------
// Banded attention, fp16 mma + ldmatrix. Grid (2,256). Warps 2(M) x 4(N).
// SMEM region A is time-shared: phase-1 Q/K tiles -> fp32 S -> phase-2 V tiles.
// Persistent fp16 P lives above it. attn<192> now fits 2 CTAs/SM.
// ---------------------------------------------------------------------------
template <int W>
__global__ void __launch_bounds__(256) attn_kernel()
{
    constexpr int NF = W / 32;            // phase1 n-frags per warp; phase2 jtiles
    constexpr int SSTF = W + 4;           // Ss stride (floats)
    constexpr int SSTH = W + 8;           // Ph stride (halves)
    constexpr int QS_SZ = 64 * 80;        // Q stage bytes
    constexpr int QK_ST = (64 + W) * 80;  // phase1 stage stride
    constexpr int V_ST = 32 * 528;        // phase2 stage stride (32 j x 264 halves)
    constexpr int T1 = 3 * QK_ST;         // phase1 tiles
    constexpr int T2 = 64 * SSTF * 4;     // fp32 S
    constexpr int T3 = 3 * V_ST;          // phase2 V tiles
    constexpr int REGA = (T1 > T2 ? (T1 > T3 ? T1 : T3) : (T2 > T3 ? T2 : T3));
    constexpr int OFF_P = REGA;           // persistent fp16 P

    extern __shared__ unsigned char smraw[];
    const uint32_t smb = smem_u32(smraw);
    float* Ss = (float*)smraw;            // aliases region A

    const int tid = threadIdx.x, lane = tid & 31, wid = tid >> 5;
    const int g = lane >> 2, t = lane & 3;
    const int wm = wid & 1, wn = wid >> 1;
    const int bs = blockIdx.y;
    const int qt = (W == 128) ? (blockIdx.x ? 3 : 0) : (1 + blockIdx.x);
    const int i0 = qt * 64;
    const int jlo = (i0 >= 64) ? (i0 - 64) : 0;

    const __half* Qg = g_qh + (size_t)(bs * 256 + i0) * 512;
    const __half* Kg = g_kh + (size_t)(bs * 256 + jlo) * 512;
    const __half* Vg = g_vh + (size_t)(bs * 256 + jlo) * 512;

    // ---------------- phase 1: S = Q K^T ----------------
    auto ldqk = [&](int kt, int s) {
        const int k0 = kt * 32;
        const uint32_t qd = smb + s * QK_ST;
        const uint32_t kd = qd + QS_SZ;
        {
            int row = tid >> 2, hc = (tid & 3) * 8;
            cp16(qd + row * 80 + hc * 2, Qg + (size_t)row * 512 + k0 + hc);
        }
#pragma unroll
        for (int i = 0; i < W / 64; i++) {
            int u = tid + i * 256;
            int row = u >> 2, hc = (u & 3) * 8;
            cp16(kd + row * 80 + hc * 2, Kg + (size_t)row * 512 + k0 + hc);
        }
        cp_commit();
    };

    float acc[2][NF][4];
#pragma unroll
    for (int mf = 0; mf < 2; mf++)
#pragma unroll
        for (int nf = 0; nf < NF; nf++)
#pragma unroll
            for (int r = 0; r < 4; r++) acc[mf][nf][r] = 0.f;

    ldqk(0, 0);
    ldqk(1, 1);

    for (int kt = 0; kt < 16; kt++) {
        if (kt < 15) cp_wait<1>(); else cp_wait<0>();
        __syncthreads();
        if (kt + 2 < 16) ldqk(kt + 2, (kt + 2) % 3);

        const uint32_t qb = smb + (kt % 3) * QK_ST;
        const uint32_t kb = qb + QS_SZ;
#pragma unroll
        for (int kk = 0; kk < 2; kk++) {
            uint4 a[2];
#pragma unroll
            for (int mf = 0; mf < 2; mf++)
                ldsm4(a[mf], qb + (wm * 32 + mf * 16 + (lane & 15)) * 80 +
                              kk * 32 + (lane >> 4) * 16);
#pragma unroll
            for (int np = 0; np < NF / 2; np++) {
                uint4 bm;
                ldsm4(bm, kb + (wn * (W / 4) + (np * 2 + (lane >> 4)) * 8 + (lane & 7)) * 80 +
                           kk * 32 + ((lane >> 3) & 1) * 16);
                mma16(acc[0][np * 2], a[0], bm.x, bm.y);
                mma16(acc[1][np * 2], a[1], bm.x, bm.y);
                mma16(acc[0][np * 2 + 1], a[0], bm.z, bm.w);
                mma16(acc[1][np * 2 + 1], a[1], bm.z, bm.w);
            }
        }
    }
    __syncthreads();   // all warps done reading Q/K tiles; S overwrites region A

    // scale + band mask + store S (fp32) to smem
#pragma unroll
    for (int mf = 0; mf < 2; mf++)
#pragma unroll
        for (int nf = 0; nf < NF; nf++)
#pragma unroll
            for (int r = 0; r < 4; r++) {
                int row = wm * 32 + mf * 16 + g + ((r & 2) ? 8 : 0);
                int jl = wn * (W / 4) + nf * 8 + t * 2 + (r & 1);
                int i = i0 + row, j = jlo + jl;
                float v = acc[mf][nf][r] * 0.125f;
                if (j < i - 64 || j > i + 64) v = -3.0e38f;
                Ss[row * SSTF + jl] = v;
            }
    __syncthreads();

    // fp32 softmax: 4 threads per row; write fp16 P
    {
        const int row = tid >> 2, part = tid & 3;
        float* rp = Ss + row * SSTF;
        __half* pp = (__half*)(smraw + OFF_P) + row * SSTH;
        float mx = -3.4e38f;
        for (int jl = part; jl < W; jl += 4) mx = fmaxf(mx, rp[jl]);
        mx = fmaxf(mx, __shfl_xor_sync(0xffffffffu, mx, 1));
        mx = fmaxf(mx, __shfl_xor_sync(0xffffffffu, mx, 2));
        float sm = 0.f;
        for (int jl = part; jl < W; jl += 4) {
            float e = __expf(rp[jl] - mx);
            rp[jl] = e;
            sm += e;
        }
        sm += __shfl_xor_sync(0xffffffffu, sm, 1);
        sm += __shfl_xor_sync(0xffffffffu, sm, 2);
        float inv = 1.0f / sm;
        for (int jl = part; jl < W; jl += 4) pp[jl] = __float2half_rn(rp[jl] * inv);
    }
    __syncthreads();   // S dead; V tiles may overwrite region A

    // ---------------- phase 2: O = P V ----------------
    const int b = bs >> 5, s = bs & 31;

    for (int half = 0; half < 2; half++) {
        __syncthreads();   // tile region free (phase1 / prev half readers done)

        auto ldv = [&](int jt, int st) {
            const uint32_t vd = smb + st * V_ST;
#pragma unroll
            for (int i = 0; i < 4; i++) {
                int u = tid + i * 256;
                int row = u >> 5, ch = u & 31;
                cp16(vd + row * 528 + ch * 16,
                     Vg + (size_t)(jt * 32 + row) * 512 + half * 256 + ch * 8);
            }
            cp_commit();
        };

        float acc2[2][8][4];
#pragma unroll
        for (int mf = 0; mf < 2; mf++)
#pragma unroll
            for (int nf = 0; nf < 8; nf++)
#pragma unroll
                for (int r = 0; r < 4; r++) acc2[mf][nf][r] = 0.f;

        ldv(0, 0);
        ldv(1, 1);

        for (int jt = 0; jt < NF; jt++) {
            if (jt < NF - 1) cp_wait<1>(); else cp_wait<0>();
            __syncthreads();
            if (jt + 2 < NF) ldv(jt + 2, (jt + 2) % 3);

            const uint32_t vb = smb + (jt % 3) * V_ST;
#pragma unroll
            for (int kk = 0; kk < 2; kk++) {
                uint4 a[2];
#pragma unroll
                for (int mf = 0; mf < 2; mf++)
                    ldsm4(a[mf], smb + OFF_P + (wm * 32 + mf * 16 + (lane & 15)) * (SSTH * 2) +
                                  (jt * 32 + kk * 16 + (lane >> 4) * 8) * 2);
#pragma unroll
                for (int np = 0; np < 4; np++) {
                    uint4 bm;
                    ldsm4t(bm, vb + (kk * 16 + ((lane >> 3) & 1) * 8 + (lane & 7)) * 528 +
                                (wn * 64 + (np * 2 + (lane >> 4)) * 8) * 2);
                    mma16(acc2[0][np * 2], a[0], bm.x, bm.y);
                    mma16(acc2[1][np * 2], a[1], bm.x, bm.y);
                    mma16(acc2[0][np * 2 + 1], a[0], bm.z, bm.w);
                    mma16(acc2[1][np * 2 + 1], a[1], bm.z, bm.w);
                }
            }
        }

#pragma unroll
        for (int mf = 0; mf < 2; mf++)
#pragma unroll
            for (int nf = 0; nf < 8; nf++)
#pragma unroll
                for (int rp = 0; rp < 2; rp++) {
                    int row = wm * 32 + mf * 16 + g + rp * 8;
                    int c = half * 256 + wn * 64 + nf * 8 + t * 2;
                    int m = b * 8192 + (i0 + row) * 32 + s;
                    store_attn_packed_h2(m, c, acc2[mf][nf][rp * 2], acc2[mf][nf][rp * 2 + 1]);
                }
    }
}

// ---------------------------------------------------------------------------
extern "C" void kernel_launch(void* const* d_in, const int* in_sizes, int n_in,
                              void* d_out, int out_size)
{
    const float* x  = (const float*)d_in[0];
    const float* Wq = (const float*)d_in[1];
    const float* bq = (const float*)d_in[2];
    const float* Wp = (const float*)d_in[3];
    const float* bp = (const float*)d_in[4];
    float* out = (float*)d_out;

    void *pxr, *pwq, *pwp, *pattn;
    cudaGetSymbolAddress(&pxr, g_xr);
    cudaGetSymbolAddress(&pwq, g_wq);
    cudaGetSymbolAddress(&pwp, g_wp);
    cudaGetSymbolAddress(&pattn, g_attn);

    const int smG = 4 * 16384;        // 65536 (4-stage)
    const int smA128 = 68096;         // REGA 50688 + Ph 17408  -> 2 CTAs/SM
    const int smA192 = 87040;         // REGA 61440 + Ph 25600  -> 2 CTAs/SM

    cudaFuncSetAttribute(tc_gemm<0>, cudaFuncAttributeMaxDynamicSharedMemorySize, smG);
    cudaFuncSetAttribute(tc_gemm<1>, cudaFuncAttributeMaxDynamicSharedMemorySize, smG);
    cudaFuncSetAttribute(attn_kernel<128>, cudaFuncAttributeMaxDynamicSharedMemorySize, smA128);
    cudaFuncSetAttribute(attn_kernel<192>, cudaFuncAttributeMaxDynamicSharedMemorySize, smA192);

    // 0) pack + fp16-round operands into m16n8k16 fragment order
    pack_x<<<16384, 256>>>(x, (uint4*)pxr);
    pack_w<1536><<<384, 256>>>(Wq, (uint4*)pwq);
    pack_w<512><<<128, 256>>>(Wp, (uint4*)pwp);

    // 1) QKV projection (fp16 mma) -> canonical fp16 Q/K/V (half2 stores)
    tc_gemm<0><<<dim3(12, 512), 256, smG>>>((const uint4*)pxr, (const uint4*)pwq, bq, nullptr);

    // 2) banded attention (fp16 mma + ldmatrix; writes fp16-packed g_attn)
    attn_kernel<128><<<dim3(2, 256), 256, smA128>>>();
    attn_kernel<192><<<dim3(2, 256), 256, smA192>>>();

    // 3) output projection (fp16 mma)
    tc_gemm<1><<<dim3(4, 512), 256, smG>>>((const uint4*)pattn, (const uint4*)pwp, bp, out);
}

// round 11
// speedup vs baseline: 1.7345x; 1.0662x over previous
#include <cuda_runtime.h>
#include <cuda_fp16.h>
#include <cstdint>

#define DEVI __device__ __forceinline__

// ---------------------------------------------------------------------------
// Scratch (device globals)
// ---------------------------------------------------------------------------
__device__ __half g_qh[33554432];   // [bs][blk][c] canonical fp16
__device__ __half g_kh[33554432];   // [bs][blk][c]
__device__ __half g_vh[33554432];   // [bs][blk][c]  (transpose via ldmatrix.trans)
__device__ float g_attn[33554432];  // aliased __half: attention out, packed A-frags
__device__ float g_xr[33554432];    // aliased __half: x packed A-frags
__device__ float g_wq[786432];      // aliased __half: W_qkv packed B-frags
__device__ float g_wp[262144];      // aliased __half: W_proj packed B-frags

DEVI uint32_t smem_u32(const void* p) {
    uint32_t a;
    asm("{ .reg .u64 t; cvta.to.shared.u64 t, %1; cvt.u32.u64 %0, t; }" : "=r"(a) : "l"(p));
    return a;
}
DEVI uint4 lds128(uint32_t a) {
    uint4 v;
    asm volatile("ld.shared.v4.u32 {%0,%1,%2,%3}, [%4];"
                 : "=r"(v.x), "=r"(v.y), "=r"(v.z), "=r"(v.w) : "r"(a));
    return v;
}
DEVI void ldsm4(uint4& r, uint32_t a) {
    asm volatile("ldmatrix.sync.aligned.m8n8.x4.shared.b16 {%0,%1,%2,%3}, [%4];"
                 : "=r"(r.x), "=r"(r.y), "=r"(r.z), "=r"(r.w) : "r"(a));
}
DEVI void ldsm4t(uint4& r, uint32_t a) {
    asm volatile("ldmatrix.sync.aligned.m8n8.x4.trans.shared.b16 {%0,%1,%2,%3}, [%4];"
                 : "=r"(r.x), "=r"(r.y), "=r"(r.z), "=r"(r.w) : "r"(a));
}
DEVI void cp16(uint32_t s, const void* g) {
    asm volatile("cp.async.cg.shared.global [%0], [%1], 16;" :: "r"(s), "l"(g));
}
DEVI void cp_commit() { asm volatile("cp.async.commit_group;"); }
template <int N> DEVI void cp_wait() { asm volatile("cp.async.wait_group %0;" :: "n"(N)); }

// fp16 mma m16n8k16, fp32 accum
DEVI void mma16(float* d, const uint4& a, unsigned b0, unsigned b1) {
    asm("mma.sync.aligned.m16n8k16.row.col.f32.f16.f16.f32 "
        "{%0,%1,%2,%3}, {%4,%5,%6,%7}, {%8,%9}, {%0,%1,%2,%3};"
        : "+f"(d[0]), "+f"(d[1]), "+f"(d[2]), "+f"(d[3])
        : "r"(a.x), "r"(a.y), "r"(a.z), "r"(a.w), "r"(b0), "r"(b1));
}

DEVI unsigned pack2(float lo, float hi) {
    __half2 h = __floats2half2_rn(lo, hi);
    return *(unsigned*)&h;
}

// ---------------------------------------------------------------------------
// fp16 fragment packs for the dense GEMMs (R5-proven layouts)
// ---------------------------------------------------------------------------
__global__ void pack_x(const float* __restrict__ x, uint4* __restrict__ o) {
    int u = blockIdx.x * 256 + threadIdx.x;
    int l = u & 31, kk = (u >> 5) & 1, mf = (u >> 6) & 1, wm = (u >> 7) & 3;
    int kt = (u >> 9) & 15, mt = u >> 13;
    int r = mt * 128 + wm * 32 + mf * 16 + (l >> 2);
    int k = kt * 32 + kk * 16 + (l & 3) * 2;
    const float* p = x + (size_t)r * 512 + k;
    uint4 v;
    v.x = pack2(p[0], p[1]);
    v.y = pack2(p[8 * 512], p[8 * 512 + 1]);
    v.z = pack2(p[8], p[9]);
    v.w = pack2(p[8 * 512 + 8], p[8 * 512 + 9]);
    o[u] = v;
}

template <int NTOT>
__global__ void pack_w(const float* __restrict__ W, uint4* __restrict__ o) {
    int u = blockIdx.x * 256 + threadIdx.x;
    int l = u & 31, kk = (u >> 5) & 1, nfp = (u >> 6) & 3, wn = (u >> 8) & 1;
    int kt = (u >> 9) & 15, nt = u >> 13;
    int c = nt * 128 + wn * 64 + nfp * 16 + (l >> 2);
    int k = kt * 32 + kk * 16 + (l & 3) * 2;
    uint4 v;
    v.x = pack2(W[(size_t)k * NTOT + c], W[(size_t)(k + 1) * NTOT + c]);
    v.y = pack2(W[(size_t)(k + 8) * NTOT + c], W[(size_t)(k + 9) * NTOT + c]);
    v.z = pack2(W[(size_t)k * NTOT + c + 8], W[(size_t)(k + 1) * NTOT + c + 8]);
    v.w = pack2(W[(size_t)(k + 8) * NTOT + c + 8], W[(size_t)(k + 9) * NTOT + c + 8]);
    o[u] = v;
}

// Scatter an adjacent-c pair into packed-A layout as one half2 store.
DEVI void store_attn_packed_h2(int m, int c, float v0, float v1) {
    int mt = m >> 7, rr = m & 127;
    int wm = rr >> 5, mf = (rr >> 4) & 1, e0 = (rr >> 3) & 1, g = rr & 7;
    int kt = c >> 5, ck = c & 31;
    int kk = (ck >> 4) & 1, e1 = (ck >> 3) & 1, t = (ck >> 1) & 3;
    size_t u = ((size_t)(mt * 16 + kt)) * 512 + wm * 128 + mf * 64 + kk * 32 + g * 4 + t;
    *(__half2*)((__half*)g_attn + (u * 4 + e1 * 2 + e0) * 2) = __floats2half2_rn(v0, v1);
}

// ---------------------------------------------------------------------------
// fp16 GEMM: CTA 128x128, warps 4(M)x2(N), 3-stage cp.async (R8-proven).
// EPI==0: qkv -> canonical fp16 Q/K/V via paired half2 stores.  EPI==1: fp32 out.
// ---------------------------------------------------------------------------
template <int EPI>
__global__ void __launch_bounds__(256, 2) tc_gemm(
    const uint4* __restrict__ Apk, const uint4* __restrict__ Bpk,
    const float* __restrict__ bias, float* __restrict__ out)
{
    extern __shared__ unsigned char sm[];
    const uint32_t smb = smem_u32(sm);
    const int tid = threadIdx.x, lane = tid & 31, wid = tid >> 5;
    const int wm = wid & 3, wn = wid >> 2;
    const int nt = blockIdx.x, mt = blockIdx.y;

    const uint4* Ag = Apk + (size_t)mt * 8192;
    const uint4* Bg = Bpk + (size_t)nt * 8192;

    auto load_tile = [&](int kt, int s) {
        const uint32_t dst = smb + s * 16384;
        const uint4* sa = Ag + kt * 512;
        const uint4* sb = Bg + kt * 512;
        cp16(dst + tid * 16, sa + tid);
        cp16(dst + (tid + 256) * 16, sa + tid + 256);
        cp16(dst + 8192 + tid * 16, sb + tid);
        cp16(dst + 8192 + (tid + 256) * 16, sb + tid + 256);
        cp_commit();
    };

    float acc[2][8][4];
#pragma unroll
    for (int mf = 0; mf < 2; mf++)
#pragma unroll
        for (int nf = 0; nf < 8; nf++)
#pragma unroll
            for (int r = 0; r < 4; r++) acc[mf][nf][r] = 0.f;

    load_tile(0, 0);
    load_tile(1, 1);

    for (int kt = 0; kt < 16; kt++) {
        if (kt < 15) cp_wait<1>(); else cp_wait<0>();
        __syncthreads();
        if (kt + 2 < 16) load_tile(kt + 2, (kt + 2) % 3);

        const uint32_t st = smb + (kt % 3) * 16384;
        const uint32_t aB = st + (wm * 128 + lane) * 16;
        const uint32_t bB = st + 8192 + (wn * 256 + lane) * 16;
#pragma unroll
        for (int kk = 0; kk < 2; kk++) {
            uint4 a0 = lds128(aB + kk * 512);
            uint4 a1 = lds128(aB + 1024 + kk * 512);
            uint4 b0 = lds128(bB + kk * 512);
            uint4 b1 = lds128(bB + 1024 + kk * 512);
            uint4 b2 = lds128(bB + 2048 + kk * 512);
            uint4 b3 = lds128(bB + 3072 + kk * 512);
            mma16(acc[0][0], a0, b0.x, b0.y);
            mma16(acc[0][1], a0, b0.z, b0.w);
            mma16(acc[0][2], a0, b1.x, b1.y);
            mma16(acc[0][3], a0, b1.z, b1.w);
            mma16(acc[0][4], a0, b2.x, b2.y);
            mma16(acc[0][5], a0, b2.z, b2.w);
            mma16(acc[0][6], a0, b3.x, b3.y);
            mma16(acc[0][7], a0, b3.z, b3.w);
            mma16(acc[1][0], a1, b0.x, b0.y);
            mma16(acc[1][1], a1, b0.z, b0.w);
            mma16(acc[1][2], a1, b1.x, b1.y);
            mma16(acc[1][3], a1, b1.z, b1.w);
            mma16(acc[1][4], a1, b2.x, b2.y);
            mma16(acc[1][5], a1, b2.z, b2.w);
            mma16(acc[1][6], a1, b3.x, b3.y);
            mma16(acc[1][7], a1, b3.z, b3.w);
        }
    }

#pragma unroll
    for (int mf = 0; mf < 2; mf++)
#pragma unroll
        for (int nf = 0; nf < 8; nf++)
#pragma unroll
            for (int rp = 0; rp < 2; rp++) {
                int row = mt * 128 + wm * 32 + mf * 16 + (lane >> 2) + rp * 8;
                int cc = nt * 128 + wn * 64 + nf * 8 + (lane & 3) * 2;
                float v0 = acc[mf][nf][rp * 2] + bias[cc];
                float v1 = acc[mf][nf][rp * 2 + 1] + bias[cc + 1];
                if (EPI == 0) {
                    int b = row >> 13, n = row & 8191;
                    int blk = n >> 5, s = n & 31;
                    int bs = b * 32 + s;
                    int hh = cc / 192, rr = cc - hh * 192;
                    int kind = rr >> 6, c = hh * 64 + (rr & 63);
                    __half2 hv = __floats2half2_rn(v0, v1);
                    __half* dp = (kind == 0) ? g_qh : (kind == 1) ? g_kh : g_vh;
                    *(__half2*)(dp + ((size_t)(bs * 256 + blk)) * 512 + c) = hv;
                } else {
                    float* db = out + (size_t)row * 512 + cc;
                    db[0] = v0;
                    db[1] = v1;
                }
            }
}

// ---------------------------------------------------------------------------
// Banded attention body, fp16 mma + ldmatrix. 8 warps: 2(M) x 4(N).
// SMEM region A time-shared: phase-1 Q/K tiles -> fp32 S -> phase-2 V tiles.
// Persistent fp16 P above it. Called per-(bs, qt) from the merged kernel.
// ---------------------------------------------------------------------------
template <int W>
DEVI void attn_body(int bs, int qt, const uint32_t smb, unsigned char* smraw)
{
    constexpr int NF = W / 32;
    constexpr int SSTF = W + 4;
    constexpr int SSTH = W + 8;
    constexpr int QS_SZ = 64 * 80;
    constexpr int QK_ST = (64 + W) * 80;
    constexpr int V_ST = 32 * 528;
    // uniform region-A size across W variants (max of all uses, W=192):
    constexpr int REGA = 61440;
    constexpr int OFF_P = REGA;

    float* Ss = (float*)smraw;

    const int tid = threadIdx.x, lane = tid & 31, wid = tid >> 5;
    const int g = lane >> 2, t = lane & 3;
    const int wm = wid & 1, wn = wid >> 1;
    const int i0 = qt * 64;
    const int jlo = (i0 >= 64) ? (i0 - 64) : 0;

    const __half* Qg = g_qh + (size_t)(bs * 256 + i0) * 512;
    const __half* Kg = g_kh + (size_t)(bs * 256 + jlo) * 512;
    const __half* Vg = g_vh + (size_t)(bs * 256 + jlo) * 512;

    // ---------------- phase 1: S = Q K^T ----------------
    auto ldqk = [&](int kt, int s) {
        const int k0 = kt * 32;
        const uint32_t qd = smb + s * QK_ST;
        const uint32_t kd = qd + QS_SZ;
        {
            int row = tid >> 2, hc = (tid & 3) * 8;
            cp16(qd + row * 80 + hc * 2, Qg + (size_t)row * 512 + k0 + hc);
        }
#pragma unroll
        for (int i = 0; i < W / 64; i++) {
            int u = tid + i * 256;
            int row = u >> 2, hc = (u & 3) * 8;
            cp16(kd + row * 80 + hc * 2, Kg + (size_t)row * 512 + k0 + hc);
        }
        cp_commit();
    };

    float acc[2][NF][4];
#pragma unroll
    for (int mf = 0; mf < 2; mf++)
#pragma unroll
        for (int nf = 0; nf < NF; nf++)
#pragma unroll
            for (int r = 0; r < 4; r++) acc[mf][nf][r] = 0.f;

    ldqk(0, 0);
    ldqk(1, 1);

    for (int kt = 0; kt < 16; kt++) {
        if (kt < 15) cp_wait<1>(); else cp_wait<0>();
        __syncthreads();
        if (kt + 2 < 16) ldqk(kt + 2, (kt + 2) % 3);

        const uint32_t qb = smb + (kt % 3) * QK_ST;
        const uint32_t kb = qb + QS_SZ;
#pragma unroll
        for (int kk = 0; kk < 2; kk++) {
            uint4 a[2];
#pragma unroll
            for (int mf = 0; mf < 2; mf++)
                ldsm4(a[mf], qb + (wm * 32 + mf * 16 + (lane & 15)) * 80 +
                              kk * 32 + (lane >> 4) * 16);
#pragma unroll
            for (int np = 0; np < NF / 2; np++) {
                uint4 bm;
                ldsm4(bm, kb + (wn * (W / 4) + (np * 2 + (lane >> 4)) * 8 + (lane & 7)) * 80 +
                           kk * 32 + ((lane >> 3) & 1) * 16);
                mma16(acc[0][np * 2], a[0], bm.x, bm.y);
                mma16(acc[1][np * 2], a[1], bm.x, bm.y);
                mma16(acc[0][np * 2 + 1], a[0], bm.z, bm.w);
                mma16(acc[1][np * 2 + 1], a[1], bm.z, bm.w);
            }
        }
    }
    __syncthreads();   // tiles dead; S overwrites region A

    // scale + band mask + store S (fp32) to smem
#pragma unroll
    for (int mf = 0; mf < 2; mf++)
#pragma unroll
        for (int nf = 0; nf < NF; nf++)
#pragma unroll
            for (int r = 0; r < 4; r++) {
                int row = wm * 32 + mf * 16 + g + ((r & 2) ? 8 : 0);
                int jl = wn * (W / 4) + nf * 8 + t * 2 + (r & 1);
                int i = i0 + row, j = jlo + jl;
                float v = acc[mf][nf][r] * 0.125f;
                if (j < i - 64 || j > i + 64) v = -3.0e38f;
                Ss[row * SSTF + jl] = v;
            }
    __syncthreads();

    // fp32 softmax: 4 threads per row; write fp16 P
    {
        const int row = tid >> 2, part = tid & 3;
        float* rp = Ss + row * SSTF;
        __half* pp = (__half*)(smraw + OFF_P) + row * SSTH;
        float mx = -3.4e38f;
        for (int jl = part; jl < W; jl += 4) mx = fmaxf(mx, rp[jl]);
        mx = fmaxf(mx, __shfl_xor_sync(0xffffffffu, mx, 1));
        mx = fmaxf(mx, __shfl_xor_sync(0xffffffffu, mx, 2));
        float sm = 0.f;
        for (int jl = part; jl < W; jl += 4) {
            float e = __expf(rp[jl] - mx);
            rp[jl] = e;
            sm += e;
        }
        sm += __shfl_xor_sync(0xffffffffu, sm, 1);
        sm += __shfl_xor_sync(0xffffffffu, sm, 2);
        float inv = 1.0f / sm;
        for (int jl = part; jl < W; jl += 4) pp[jl] = __float2half_rn(rp[jl] * inv);
    }
    __syncthreads();   // S dead; V tiles may overwrite region A

    // ---------------- phase 2: O = P V ----------------
    const int b = bs >> 5, s = bs & 31;

    for (int half = 0; half < 2; half++) {
        __syncthreads();   // tile region free

        auto ldv = [&](int jt, int st) {
            const uint32_t vd = smb + st * V_ST;
#pragma unroll
            for (int i = 0; i < 4; i++) {
                int u = tid + i * 256;
                int row = u >> 5, ch = u & 31;
                cp16(vd + row * 528 + ch * 16,
                     Vg + (size_t)(jt * 32 + row) * 512 + half * 256 + ch * 8);
            }
            cp_commit();
        };

        float acc2[2][8][4];
#pragma unroll
        for (int mf = 0; mf < 2; mf++)
#pragma unroll
            for (int nf = 0; nf < 8; nf++)
#pragma unroll
                for (int r = 0; r < 4; r++) acc2[mf][nf][r] = 0.f;

        ldv(0, 0);
        ldv(1, 1);

        for (int jt = 0; jt < NF; jt++) {
            if (jt < NF - 1) cp_wait<1>(); else cp_wait<0>();
            __syncthreads();
            if (jt + 2 < NF) ldv(jt + 2, (jt + 2) % 3);

            const uint32_t vb = smb + (jt % 3) * V_ST;
#pragma unroll
            for (int kk = 0; kk < 2; kk++) {
                uint4 a[2];
#pragma unroll
                for (int mf = 0; mf < 2; mf++)
                    ldsm4(a[mf], smb + OFF_P + (wm * 32 + mf * 16 + (lane & 15)) * (SSTH * 2) +
                                  (jt * 32 + kk * 16 + (lane >> 4) * 8) * 2);
#pragma unroll
                for (int np = 0; np < 4; np++) {
                    uint4 bm;
                    ldsm4t(bm, vb + (kk * 16 + ((lane >> 3) & 1) * 8 + (lane & 7)) * 528 +
                                (wn * 64 + (np * 2 + (lane >> 4)) * 8) * 2);
                    mma16(acc2[0][np * 2], a[0], bm.x, bm.y);
                    mma16(acc2[1][np * 2], a[1], bm.x, bm.y);
                    mma16(acc2[0][np * 2 + 1], a[0], bm.z, bm.w);
                    mma16(acc2[1][np * 2 + 1], a[1], bm.z, bm.w);
                }
            }
        }

#pragma unroll
        for (int mf = 0; mf < 2; mf++)
#pragma unroll
            for (int nf = 0; nf < 8; nf++)
#pragma unroll
                for (int rp = 0; rp < 2; rp++) {
                    int row = wm * 32 + mf * 16 + g + rp * 8;
                    int c = half * 256 + wn * 64 + nf * 8 + t * 2;
                    int m = b * 8192 + (i0 + row) * 32 + s;
                    store_attn_packed_h2(m, c, acc2[mf][nf][rp * 2], acc2[mf][nf][rp * 2 + 1]);
                }
    }
}

// Merged attention: 1024 CTAs in one launch. [0,512): W=128 (qt 0/3);
// [512,1024): W=192 (qt 1/2). One wave train, one tail.
__global__ void __launch_bounds__(256) attn_all()
{
    extern __shared__ unsigned char smraw[];
    const uint32_t smb = smem_u32(smraw);
    const int idx = blockIdx.x;
    if (idx < 512) {
        const int bs = idx >> 1;
        const int qt = (idx & 1) ? 3 : 0;
        attn_body<128>(bs, qt, smb, smraw);
    } else {
        const int r = idx - 512;
        const int bs = r >> 1;
        const int qt = 1 + (r & 1);
        attn_body<192>(bs, qt, smb, smraw);
    }
}

// ---------------------------------------------------------------------------
extern "C" void kernel_launch(void* const* d_in, const int* in_sizes, int n_in,
                              void* d_out, int out_size)
{
    const float* x  = (const float*)d_in[0];
    const float* Wq = (const float*)d_in[1];
    const float* bq = (const float*)d_in[2];
    const float* Wp = (const float*)d_in[3];
    const float* bp = (const float*)d_in[4];
    float* out = (float*)d_out;

    void *pxr, *pwq, *pwp, *pattn;
    cudaGetSymbolAddress(&pxr, g_xr);
    cudaGetSymbolAddress(&pwq, g_wq);
    cudaGetSymbolAddress(&pwp, g_wp);
    cudaGetSymbolAddress(&pattn, g_attn);

    const int smG = 3 * 16384;        // 49152 (3-stage, R8-proven)
    const int smA = 61440 + 25600;    // REGA(192) + Ph(192) = 87040 -> 2 CTAs/SM

    cudaFuncSetAttribute(tc_gemm<0>, cudaFuncAttributeMaxDynamicSharedMemorySize, smG);
    cudaFuncSetAttribute(tc_gemm<1>, cudaFuncAttributeMaxDynamicSharedMemorySize, smG);
    cudaFuncSetAttribute(attn_all, cudaFuncAttributeMaxDynamicSharedMemorySize, smA);

    // 0) pack + fp16-round operands into m16n8k16 fragment order
    pack_x<<<16384, 256>>>(x, (uint4*)pxr);
    pack_w<1536><<<384, 256>>>(Wq, (uint4*)pwq);
    pack_w<512><<<128, 256>>>(Wp, (uint4*)pwp);

    // 1) QKV projection (fp16 mma) -> canonical fp16 Q/K/V (half2 stores)
    tc_gemm<0><<<dim3(12, 512), 256, smG>>>((const uint4*)pxr, (const uint4*)pwq, bq, nullptr);

    // 2) merged banded attention (single launch, one tail wave)
    attn_all<<<1024, 256, smA>>>();

    // 3) output projection (fp16 mma)
    tc_gemm<1><<<dim3(4, 512), 256, smG>>>((const uint4*)pattn, (const uint4*)pwp, bp, out);
}

// round 12
// speedup vs baseline: 1.7690x; 1.0199x over previous
#include <cuda_runtime.h>
#include <cuda_fp16.h>
#include <cstdint>

#define DEVI __device__ __forceinline__

// ---------------------------------------------------------------------------
// Scratch (device globals)
// ---------------------------------------------------------------------------
__device__ __half g_qh[33554432];   // [bs][blk][c] canonical fp16
__device__ __half g_kh[33554432];   // [bs][blk][c]
__device__ __half g_vh[33554432];   // [bs][blk][c]  (transpose via ldmatrix.trans)
__device__ float g_attn[33554432];  // aliased __half: attention out, packed A-frags
__device__ float g_xr[33554432];    // aliased __half: x packed A-frags
__device__ float g_wq[786432];      // aliased __half: W_qkv packed B-frags
__device__ float g_wp[262144];      // aliased __half: W_proj packed B-frags

DEVI uint32_t smem_u32(const void* p) {
    uint32_t a;
    asm("{ .reg .u64 t; cvta.to.shared.u64 t, %1; cvt.u32.u64 %0, t; }" : "=r"(a) : "l"(p));
    return a;
}
DEVI uint4 lds128(uint32_t a) {
    uint4 v;
    asm volatile("ld.shared.v4.u32 {%0,%1,%2,%3}, [%4];"
                 : "=r"(v.x), "=r"(v.y), "=r"(v.z), "=r"(v.w) : "r"(a));
    return v;
}
DEVI void ldsm4(uint4& r, uint32_t a) {
    asm volatile("ldmatrix.sync.aligned.m8n8.x4.shared.b16 {%0,%1,%2,%3}, [%4];"
                 : "=r"(r.x), "=r"(r.y), "=r"(r.z), "=r"(r.w) : "r"(a));
}
DEVI void ldsm4t(uint4& r, uint32_t a) {
    asm volatile("ldmatrix.sync.aligned.m8n8.x4.trans.shared.b16 {%0,%1,%2,%3}, [%4];"
                 : "=r"(r.x), "=r"(r.y), "=r"(r.z), "=r"(r.w) : "r"(a));
}
DEVI void cp16(uint32_t s, const void* g) {
    asm volatile("cp.async.cg.shared.global [%0], [%1], 16;" :: "r"(s), "l"(g));
}
DEVI void cp_commit() { asm volatile("cp.async.commit_group;"); }
template <int N> DEVI void cp_wait() { asm volatile("cp.async.wait_group %0;" :: "n"(N)); }

// fp16 mma m16n8k16, fp32 accum
DEVI void mma16(float* d, const uint4& a, unsigned b0, unsigned b1) {
    asm("mma.sync.aligned.m16n8k16.row.col.f32.f16.f16.f32 "
        "{%0,%1,%2,%3}, {%4,%5,%6,%7}, {%8,%9}, {%0,%1,%2,%3};"
        : "+f"(d[0]), "+f"(d[1]), "+f"(d[2]), "+f"(d[3])
        : "r"(a.x), "r"(a.y), "r"(a.z), "r"(a.w), "r"(b0), "r"(b1));
}

DEVI unsigned pack2(float lo, float hi) {
    __half2 h = __floats2half2_rn(lo, hi);
    return *(unsigned*)&h;
}

// ---------------------------------------------------------------------------
// fp16 fragment packs for the dense GEMMs (R5-proven layouts)
// ---------------------------------------------------------------------------
__global__ void pack_x(const float* __restrict__ x, uint4* __restrict__ o) {
    int u = blockIdx.x * 256 + threadIdx.x;
    int l = u & 31, kk = (u >> 5) & 1, mf = (u >> 6) & 1, wm = (u >> 7) & 3;
    int kt = (u >> 9) & 15, mt = u >> 13;
    int r = mt * 128 + wm * 32 + mf * 16 + (l >> 2);
    int k = kt * 32 + kk * 16 + (l & 3) * 2;
    const float* p = x + (size_t)r * 512 + k;
    uint4 v;
    v.x = pack2(p[0], p[1]);
    v.y = pack2(p[8 * 512], p[8 * 512 + 1]);
    v.z = pack2(p[8], p[9]);
    v.w = pack2(p[8 * 512 + 8], p[8 * 512 + 9]);
    o[u] = v;
}

template <int NTOT>
__global__ void pack_w(const float* __restrict__ W, uint4* __restrict__ o) {
    int u = blockIdx.x * 256 + threadIdx.x;
    int l = u & 31, kk = (u >> 5) & 1, nfp = (u >> 6) & 3, wn = (u >> 8) & 1;
    int kt = (u >> 9) & 15, nt = u >> 13;
    int c = nt * 128 + wn * 64 + nfp * 16 + (l >> 2);
    int k = kt * 32 + kk * 16 + (l & 3) * 2;
    uint4 v;
    v.x = pack2(W[(size_t)k * NTOT + c], W[(size_t)(k + 1) * NTOT + c]);
    v.y = pack2(W[(size_t)(k + 8) * NTOT + c], W[(size_t)(k + 9) * NTOT + c]);
    v.z = pack2(W[(size_t)k * NTOT + c + 8], W[(size_t)(k + 1) * NTOT + c + 8]);
    v.w = pack2(W[(size_t)(k + 8) * NTOT + c + 8], W[(size_t)(k + 9) * NTOT + c + 8]);
    o[u] = v;
}

// Scatter an adjacent-c pair into packed-A layout as one half2 store.
DEVI void store_attn_packed_h2(int m, int c, float v0, float v1) {
    int mt = m >> 7, rr = m & 127;
    int wm = rr >> 5, mf = (rr >> 4) & 1, e0 = (rr >> 3) & 1, g = rr & 7;
    int kt = c >> 5, ck = c & 31;
    int kk = (ck >> 4) & 1, e1 = (ck >> 3) & 1, t = (ck >> 1) & 3;
    size_t u = ((size_t)(mt * 16 + kt)) * 512 + wm * 128 + mf * 64 + kk * 32 + g * 4 + t;
    *(__half2*)((__half*)g_attn + (u * 4 + e1 * 2 + e0) * 2) = __floats2half2_rn(v0, v1);
}

// ---------------------------------------------------------------------------
// fp16 GEMM: CTA 128x128, warps 4(M)x2(N), 3-stage cp.async (R8-proven).
// EPI==0: qkv -> canonical fp16 Q/K/V via paired half2 stores.  EPI==1: fp32 out.
// ---------------------------------------------------------------------------
template <int EPI>
__global__ void __launch_bounds__(256, 2) tc_gemm(
    const uint4* __restrict__ Apk, const uint4* __restrict__ Bpk,
    const float* __restrict__ bias, float* __restrict__ out)
{
    extern __shared__ unsigned char sm[];
    const uint32_t smb = smem_u32(sm);
    const int tid = threadIdx.x, lane = tid & 31, wid = tid >> 5;
    const int wm = wid & 3, wn = wid >> 2;
    const int nt = blockIdx.x, mt = blockIdx.y;

    const uint4* Ag = Apk + (size_t)mt * 8192;
    const uint4* Bg = Bpk + (size_t)nt * 8192;

    auto load_tile = [&](int kt, int s) {
        const uint32_t dst = smb + s * 16384;
        const uint4* sa = Ag + kt * 512;
        const uint4* sb = Bg + kt * 512;
        cp16(dst + tid * 16, sa + tid);
        cp16(dst + (tid + 256) * 16, sa + tid + 256);
        cp16(dst + 8192 + tid * 16, sb + tid);
        cp16(dst + 8192 + (tid + 256) * 16, sb + tid + 256);
        cp_commit();
    };

    float acc[2][8][4];
#pragma unroll
    for (int mf = 0; mf < 2; mf++)
#pragma unroll
        for (int nf = 0; nf < 8; nf++)
#pragma unroll
            for (int r = 0; r < 4; r++) acc[mf][nf][r] = 0.f;

    load_tile(0, 0);
    load_tile(1, 1);

    for (int kt = 0; kt < 16; kt++) {
        if (kt < 15) cp_wait<1>(); else cp_wait<0>();
        __syncthreads();
        if (kt + 2 < 16) load_tile(kt + 2, (kt + 2) % 3);

        const uint32_t st = smb + (kt % 3) * 16384;
        const uint32_t aB = st + (wm * 128 + lane) * 16;
        const uint32_t bB = st + 8192 + (wn * 256 + lane) * 16;
#pragma unroll
        for (int kk = 0; kk < 2; kk++) {
            uint4 a0 = lds128(aB + kk * 512);
            uint4 a1 = lds128(aB + 1024 + kk * 512);
            uint4 b0 = lds128(bB + kk * 512);
            uint4 b1 = lds128(bB + 1024 + kk * 512);
            uint4 b2 = lds128(bB + 2048 + kk * 512);
            uint4 b3 = lds128(bB + 3072 + kk * 512);
            mma16(acc[0][0], a0, b0.x, b0.y);
            mma16(acc[0][1], a0, b0.z, b0.w);
            mma16(acc[0][2], a0, b1.x, b1.y);
            mma16(acc[0][3], a0, b1.z, b1.w);
            mma16(acc[0][4], a0, b2.x, b2.y);
            mma16(acc[0][5], a0, b2.z, b2.w);
            mma16(acc[0][6], a0, b3.x, b3.y);
            mma16(acc[0][7], a0, b3.z, b3.w);
            mma16(acc[1][0], a1, b0.x, b0.y);
            mma16(acc[1][1], a1, b0.z, b0.w);
            mma16(acc[1][2], a1, b1.x, b1.y);
            mma16(acc[1][3], a1, b1.z, b1.w);
            mma16(acc[1][4], a1, b2.x, b2.y);
            mma16(acc[1][5], a1, b2.z, b2.w);
            mma16(acc[1][6], a1, b3.x, b3.y);
            mma16(acc[1][7], a1, b3.z, b3.w);
        }
    }

#pragma unroll
    for (int mf = 0; mf < 2; mf++)
#pragma unroll
        for (int nf = 0; nf < 8; nf++)
#pragma unroll
            for (int rp = 0; rp < 2; rp++) {
                int row = mt * 128 + wm * 32 + mf * 16 + (lane >> 2) + rp * 8;
                int cc = nt * 128 + wn * 64 + nf * 8 + (lane & 3) * 2;
                float v0 = acc[mf][nf][rp * 2] + bias[cc];
                float v1 = acc[mf][nf][rp * 2 + 1] + bias[cc + 1];
                if (EPI == 0) {
                    int b = row >> 13, n = row & 8191;
                    int blk = n >> 5, s = n & 31;
                    int bs = b * 32 + s;
                    int hh = cc / 192, rr = cc - hh * 192;
                    int kind = rr >> 6, c = hh * 64 + (rr & 63);
                    __half2 hv = __floats2half2_rn(v0, v1);
                    __half* dp = (kind == 0) ? g_qh : (kind == 1) ? g_kh : g_vh;
                    *(__half2*)(dp + ((size_t)(bs * 256 + blk)) * 512 + c) = hv;
                } else {
                    float* db = out + (size_t)row * 512 + cc;
                    db[0] = v0;
                    db[1] = v1;
                }
            }
}

// ---------------------------------------------------------------------------
// Banded attention body, fp16 mma + ldmatrix + REGISTER-RESIDENT softmax.
// 8 warps: 2(M) x 4(N). SMEM: region A time-shared (phase-1 Q/K tiles ->
// phase-2 V tiles; no fp32 S buffer any more), persistent fp16 P above it,
// then two 1KB partial arrays (pmax / psum) for the cross-warp reduction.
// ---------------------------------------------------------------------------
template <int W>
DEVI void attn_body(int bs, int qt, const uint32_t smb, unsigned char* smraw)
{
    constexpr int NF = W / 32;
    constexpr int SSTH = W + 8;
    constexpr int QS_SZ = 64 * 80;
    constexpr int QK_ST = (64 + W) * 80;
    constexpr int V_ST = 32 * 528;
    constexpr int REGA = 61440;           // max(3*QK_ST(192), 3*V_ST)
    constexpr int OFF_P = REGA;
    constexpr int OFF_R = OFF_P + 25600;  // pmax [64][4] floats
    constexpr int OFF_S = OFF_R + 1024;   // psum [64][4] floats

    const int tid = threadIdx.x, lane = tid & 31, wid = tid >> 5;
    const int g = lane >> 2, t = lane & 3;
    const int wm = wid & 1, wn = wid >> 1;
    const int i0 = qt * 64;
    const int jlo = (i0 >= 64) ? (i0 - 64) : 0;

    const __half* Qg = g_qh + (size_t)(bs * 256 + i0) * 512;
    const __half* Kg = g_kh + (size_t)(bs * 256 + jlo) * 512;
    const __half* Vg = g_vh + (size_t)(bs * 256 + jlo) * 512;

    // ---------------- phase 1: S = Q K^T ----------------
    auto ldqk = [&](int kt, int s) {
        const int k0 = kt * 32;
        const uint32_t qd = smb + s * QK_ST;
        const uint32_t kd = qd + QS_SZ;
        {
            int row = tid >> 2, hc = (tid & 3) * 8;
            cp16(qd + row * 80 + hc * 2, Qg + (size_t)row * 512 + k0 + hc);
        }
#pragma unroll
        for (int i = 0; i < W / 64; i++) {
            int u = tid + i * 256;
            int row = u >> 2, hc = (u & 3) * 8;
            cp16(kd + row * 80 + hc * 2, Kg + (size_t)row * 512 + k0 + hc);
        }
        cp_commit();
    };
    auto ldv = [&](int half, int jt, int st) {
        const uint32_t vd = smb + st * V_ST;
#pragma unroll
        for (int i = 0; i < 4; i++) {
            int u = tid + i * 256;
            int row = u >> 5, ch = u & 31;
            cp16(vd + row * 528 + ch * 16,
                 Vg + (size_t)(jt * 32 + row) * 512 + half * 256 + ch * 8);
        }
        cp_commit();
    };

    float acc[2][NF][4];
#pragma unroll
    for (int mf = 0; mf < 2; mf++)
#pragma unroll
        for (int nf = 0; nf < NF; nf++)
#pragma unroll
            for (int r = 0; r < 4; r++) acc[mf][nf][r] = 0.f;

    ldqk(0, 0);
    ldqk(1, 1);

    for (int kt = 0; kt < 16; kt++) {
        if (kt < 15) cp_wait<1>(); else cp_wait<0>();
        __syncthreads();
        if (kt + 2 < 16) ldqk(kt + 2, (kt + 2) % 3);

        const uint32_t qb = smb + (kt % 3) * QK_ST;
        const uint32_t kb = qb + QS_SZ;
#pragma unroll
        for (int kk = 0; kk < 2; kk++) {
            uint4 a[2];
#pragma unroll
            for (int mf = 0; mf < 2; mf++)
                ldsm4(a[mf], qb + (wm * 32 + mf * 16 + (lane & 15)) * 80 +
                              kk * 32 + (lane >> 4) * 16);
#pragma unroll
            for (int np = 0; np < NF / 2; np++) {
                uint4 bm;
                ldsm4(bm, kb + (wn * (W / 4) + (np * 2 + (lane >> 4)) * 8 + (lane & 7)) * 80 +
                           kk * 32 + ((lane >> 3) & 1) * 16);
                mma16(acc[0][np * 2], a[0], bm.x, bm.y);
                mma16(acc[1][np * 2], a[1], bm.x, bm.y);
                mma16(acc[0][np * 2 + 1], a[0], bm.z, bm.w);
                mma16(acc[1][np * 2 + 1], a[1], bm.z, bm.w);
            }
        }
    }
    __syncthreads();   // tiles dead; region A free for V

    // overlap: prefetch first two V tiles of half 0 under the softmax
    ldv(0, 0, 0);
    ldv(0, 1, 1);

    // ---------------- register softmax ----------------
    float* pmax = (float*)(smraw + OFF_R);
    float* psum = (float*)(smraw + OFF_S);

    // scale + mask in regs; per-(mf,e0) local row max over this warp's cols
    float mx[2][2];
#pragma unroll
    for (int mf = 0; mf < 2; mf++)
#pragma unroll
        for (int e0 = 0; e0 < 2; e0++) mx[mf][e0] = -3.4e38f;
#pragma unroll
    for (int mf = 0; mf < 2; mf++)
#pragma unroll
        for (int nf = 0; nf < NF; nf++)
#pragma unroll
            for (int r = 0; r < 4; r++) {
                int row = wm * 32 + mf * 16 + g + ((r & 2) ? 8 : 0);
                int jl = wn * (W / 4) + nf * 8 + t * 2 + (r & 1);
                int i = i0 + row, j = jlo + jl;
                float v = acc[mf][nf][r] * 0.125f;
                if (j < i - 64 || j > i + 64) v = -1.0e30f;
                acc[mf][nf][r] = v;
                mx[mf][r >> 1] = fmaxf(mx[mf][r >> 1], v);
            }
#pragma unroll
    for (int mf = 0; mf < 2; mf++)
#pragma unroll
        for (int e0 = 0; e0 < 2; e0++) {
            mx[mf][e0] = fmaxf(mx[mf][e0], __shfl_xor_sync(0xffffffffu, mx[mf][e0], 1));
            mx[mf][e0] = fmaxf(mx[mf][e0], __shfl_xor_sync(0xffffffffu, mx[mf][e0], 2));
        }
    if (t == 0) {
#pragma unroll
        for (int mf = 0; mf < 2; mf++)
#pragma unroll
            for (int e0 = 0; e0 < 2; e0++)
                pmax[(wm * 32 + mf * 16 + g + 8 * e0) * 4 + wn] = mx[mf][e0];
    }
    __syncthreads();

    // full row max, exp, local sums
    float sm[2][2];
#pragma unroll
    for (int mf = 0; mf < 2; mf++)
#pragma unroll
        for (int e0 = 0; e0 < 2; e0++) {
            float4 p4 = *(float4*)&pmax[(wm * 32 + mf * 16 + g + 8 * e0) * 4];
            float rmx = fmaxf(fmaxf(p4.x, p4.y), fmaxf(p4.z, p4.w));
            float s = 0.f;
#pragma unroll
            for (int nf = 0; nf < NF; nf++)
#pragma unroll
                for (int e1 = 0; e1 < 2; e1++) {
                    float e = __expf(acc[mf][nf][2 * e0 + e1] - rmx);
                    acc[mf][nf][2 * e0 + e1] = e;
                    s += e;
                }
            sm[mf][e0] = s;
        }
#pragma unroll
    for (int mf = 0; mf < 2; mf++)
#pragma unroll
        for (int e0 = 0; e0 < 2; e0++) {
            sm[mf][e0] += __shfl_xor_sync(0xffffffffu, sm[mf][e0], 1);
            sm[mf][e0] += __shfl_xor_sync(0xffffffffu, sm[mf][e0], 2);
        }
    if (t == 0) {
#pragma unroll
        for (int mf = 0; mf < 2; mf++)
#pragma unroll
            for (int e0 = 0; e0 < 2; e0++)
                psum[(wm * 32 + mf * 16 + g + 8 * e0) * 4 + wn] = sm[mf][e0];
    }
    __syncthreads();

    // normalize + store fp16 P
    __half* pp = (__half*)(smraw + OFF_P);
#pragma unroll
    for (int mf = 0; mf < 2; mf++)
#pragma unroll
        for (int e0 = 0; e0 < 2; e0++) {
            int row = wm * 32 + mf * 16 + g + 8 * e0;
            float4 s4 = *(float4*)&psum[row * 4];
            float inv = 1.0f / (s4.x + s4.y + s4.z + s4.w);
#pragma unroll
            for (int nf = 0; nf < NF; nf++) {
                int jl = wn * (W / 4) + nf * 8 + t * 2;
                *(__half2*)(pp + row * SSTH + jl) =
                    __floats2half2_rn(acc[mf][nf][2 * e0] * inv,
                                      acc[mf][nf][2 * e0 + 1] * inv);
            }
        }
    __syncthreads();   // P visible

    // ---------------- phase 2: O = P V ----------------
    const int b = bs >> 5, s = bs & 31;

    for (int half = 0; half < 2; half++) {
        if (half == 1) {
            __syncthreads();   // half-0 readers done with V slots
            ldv(1, 0, 0);
            ldv(1, 1, 1);
        }

        float acc2[2][8][4];
#pragma unroll
        for (int mf = 0; mf < 2; mf++)
#pragma unroll
            for (int nf = 0; nf < 8; nf++)
#pragma unroll
                for (int r = 0; r < 4; r++) acc2[mf][nf][r] = 0.f;

        for (int jt = 0; jt < NF; jt++) {
            if (jt < NF - 1) cp_wait<1>(); else cp_wait<0>();
            __syncthreads();
            if (jt + 2 < NF) ldv(half, jt + 2, (jt + 2) % 3);

            const uint32_t vb = smb + (jt % 3) * V_ST;
#pragma unroll
            for (int kk = 0; kk < 2; kk++) {
                uint4 a[2];
#pragma unroll
                for (int mf = 0; mf < 2; mf++)
                    ldsm4(a[mf], smb + OFF_P + (wm * 32 + mf * 16 + (lane & 15)) * (SSTH * 2) +
                                  (jt * 32 + kk * 16 + (lane >> 4) * 8) * 2);
#pragma unroll
                for (int np = 0; np < 4; np++) {
                    uint4 bm;
                    ldsm4t(bm, vb + (kk * 16 + ((lane >> 3) & 1) * 8 + (lane & 7)) * 528 +
                                (wn * 64 + (np * 2 + (lane >> 4)) * 8) * 2);
                    mma16(acc2[0][np * 2], a[0], bm.x, bm.y);
                    mma16(acc2[1][np * 2], a[1], bm.x, bm.y);
                    mma16(acc2[0][np * 2 + 1], a[0], bm.z, bm.w);
                    mma16(acc2[1][np * 2 + 1], a[1], bm.z, bm.w);
                }
            }
        }

#pragma unroll
        for (int mf = 0; mf < 2; mf++)
#pragma unroll
            for (int nf = 0; nf < 8; nf++)
#pragma unroll
                for (int rp = 0; rp < 2; rp++) {
                    int row = wm * 32 + mf * 16 + g + rp * 8;
                    int c = half * 256 + wn * 64 + nf * 8 + t * 2;
                    int m = b * 8192 + (i0 + row) * 32 + s;
                    store_attn_packed_h2(m, c, acc2[mf][nf][rp * 2], acc2[mf][nf][rp * 2 + 1]);
                }
    }
}

// Merged attention: 1024 CTAs in one launch. [0,512): W=128 (qt 0/3);
// [512,1024): W=192 (qt 1/2). One wave train, one tail.
__global__ void __launch_bounds__(256, 2) attn_all()
{
    extern __shared__ unsigned char smraw[];
    const uint32_t smb = smem_u32(smraw);
    const int idx = blockIdx.x;
    if (idx < 512) {
        const int bs = idx >> 1;
        const int qt = (idx & 1) ? 3 : 0;
        attn_body<128>(bs, qt, smb, smraw);
    } else {
        const int r = idx - 512;
        const int bs = r >> 1;
        const int qt = 1 + (r & 1);
        attn_body<192>(bs, qt, smb, smraw);
    }
}

// ---------------------------------------------------------------------------
extern "C" void kernel_launch(void* const* d_in, const int* in_sizes, int n_in,
                              void* d_out, int out_size)
{
    const float* x  = (const float*)d_in[0];
    const float* Wq = (const float*)d_in[1];
    const float* bq = (const float*)d_in[2];
    const float* Wp = (const float*)d_in[3];
    const float* bp = (const float*)d_in[4];
    float* out = (float*)d_out;

    void *pxr, *pwq, *pwp, *pattn;
    cudaGetSymbolAddress(&pxr, g_xr);
    cudaGetSymbolAddress(&pwq, g_wq);
    cudaGetSymbolAddress(&pwp, g_wp);
    cudaGetSymbolAddress(&pattn, g_attn);

    const int smG = 3 * 16384;             // 49152 (3-stage, R8-proven)
    const int smA = 61440 + 25600 + 2048;  // REGA + P + pmax/psum = 89088 -> 2 CTAs/SM

    cudaFuncSetAttribute(tc_gemm<0>, cudaFuncAttributeMaxDynamicSharedMemorySize, smG);
    cudaFuncSetAttribute(tc_gemm<1>, cudaFuncAttributeMaxDynamicSharedMemorySize, smG);
    cudaFuncSetAttribute(attn_all, cudaFuncAttributeMaxDynamicSharedMemorySize, smA);

    // 0) pack + fp16-round operands into m16n8k16 fragment order
    pack_x<<<16384, 256>>>(x, (uint4*)pxr);
    pack_w<1536><<<384, 256>>>(Wq, (uint4*)pwq);
    pack_w<512><<<128, 256>>>(Wp, (uint4*)pwp);

    // 1) QKV projection (fp16 mma) -> canonical fp16 Q/K/V (half2 stores)
    tc_gemm<0><<<dim3(12, 512), 256, smG>>>((const uint4*)pxr, (const uint4*)pwq, bq, nullptr);

    // 2) merged banded attention (register softmax, V-prefetch overlap)
    attn_all<<<1024, 256, smA>>>();

    // 3) output projection (fp16 mma)
    tc_gemm<1><<<dim3(4, 512), 256, smG>>>((const uint4*)pattn, (const uint4*)pwp, bp, out);
}

// round 13
// speedup vs baseline: 1.7982x; 1.0165x over previous
#include <cuda_runtime.h>
#include <cuda_fp16.h>
#include <cstdint>

#define DEVI __device__ __forceinline__

// ---------------------------------------------------------------------------
// Scratch (device globals)
// ---------------------------------------------------------------------------
__device__ __half g_qh[33554432];   // [bs][blk][c] canonical fp16
__device__ __half g_kh[33554432];   // [bs][blk][c]
__device__ __half g_vh[33554432];   // [bs][blk][c]  (transpose via ldmatrix.trans)
__device__ float g_attn[33554432];  // aliased __half: attention out, packed A-frags
__device__ float g_xr[33554432];    // aliased __half: x packed A-frags
__device__ float g_wq[786432];      // aliased __half: W_qkv packed B-frags
__device__ float g_wp[262144];      // aliased __half: W_proj packed B-frags

DEVI uint32_t smem_u32(const void* p) {
    uint32_t a;
    asm("{ .reg .u64 t; cvta.to.shared.u64 t, %1; cvt.u32.u64 %0, t; }" : "=r"(a) : "l"(p));
    return a;
}
DEVI uint4 lds128(uint32_t a) {
    uint4 v;
    asm volatile("ld.shared.v4.u32 {%0,%1,%2,%3}, [%4];"
                 : "=r"(v.x), "=r"(v.y), "=r"(v.z), "=r"(v.w) : "r"(a));
    return v;
}
DEVI void ldsm4(uint4& r, uint32_t a) {
    asm volatile("ldmatrix.sync.aligned.m8n8.x4.shared.b16 {%0,%1,%2,%3}, [%4];"
                 : "=r"(r.x), "=r"(r.y), "=r"(r.z), "=r"(r.w) : "r"(a));
}
DEVI void ldsm4t(uint4& r, uint32_t a) {
    asm volatile("ldmatrix.sync.aligned.m8n8.x4.trans.shared.b16 {%0,%1,%2,%3}, [%4];"
                 : "=r"(r.x), "=r"(r.y), "=r"(r.z), "=r"(r.w) : "r"(a));
}
DEVI void cp16(uint32_t s, const void* g) {
    asm volatile("cp.async.cg.shared.global [%0], [%1], 16;" :: "r"(s), "l"(g));
}
DEVI void cp_commit() { asm volatile("cp.async.commit_group;"); }
template <int N> DEVI void cp_wait() { asm volatile("cp.async.wait_group %0;" :: "n"(N)); }

// fp16 mma m16n8k16, fp32 accum
DEVI void mma16(float* d, const uint4& a, unsigned b0, unsigned b1) {
    asm("mma.sync.aligned.m16n8k16.row.col.f32.f16.f16.f32 "
        "{%0,%1,%2,%3}, {%4,%5,%6,%7}, {%8,%9}, {%0,%1,%2,%3};"
        : "+f"(d[0]), "+f"(d[1]), "+f"(d[2]), "+f"(d[3])
        : "r"(a.x), "r"(a.y), "r"(a.z), "r"(a.w), "r"(b0), "r"(b1));
}

DEVI unsigned pack2(float lo, float hi) {
    __half2 h = __floats2half2_rn(lo, hi);
    return *(unsigned*)&h;
}

// ---------------------------------------------------------------------------
// Fused fp16 fragment packing (one launch). Ranges:
//   [0, 16384)        : x  -> g_xr   (A-frags)
//   [16384, 16768)    : Wq -> g_wq   (B-frags, NTOT=1536)
//   [16768, 16896)    : Wp -> g_wp   (B-frags, NTOT=512)
// ---------------------------------------------------------------------------
DEVI void pack_x_body(const float* __restrict__ x, uint4* __restrict__ o, int u) {
    int l = u & 31, kk = (u >> 5) & 1, mf = (u >> 6) & 1, wm = (u >> 7) & 3;
    int kt = (u >> 9) & 15, mt = u >> 13;
    int r = mt * 128 + wm * 32 + mf * 16 + (l >> 2);
    int k = kt * 32 + kk * 16 + (l & 3) * 2;
    const float* p = x + (size_t)r * 512 + k;
    uint4 v;
    v.x = pack2(p[0], p[1]);
    v.y = pack2(p[8 * 512], p[8 * 512 + 1]);
    v.z = pack2(p[8], p[9]);
    v.w = pack2(p[8 * 512 + 8], p[8 * 512 + 9]);
    o[u] = v;
}
template <int NTOT>
DEVI void pack_w_body(const float* __restrict__ W, uint4* __restrict__ o, int u) {
    int l = u & 31, kk = (u >> 5) & 1, nfp = (u >> 6) & 3, wn = (u >> 8) & 1;
    int kt = (u >> 9) & 15, nt = u >> 13;
    int c = nt * 128 + wn * 64 + nfp * 16 + (l >> 2);
    int k = kt * 32 + kk * 16 + (l & 3) * 2;
    uint4 v;
    v.x = pack2(W[(size_t)k * NTOT + c], W[(size_t)(k + 1) * NTOT + c]);
    v.y = pack2(W[(size_t)(k + 8) * NTOT + c], W[(size_t)(k + 9) * NTOT + c]);
    v.z = pack2(W[(size_t)k * NTOT + c + 8], W[(size_t)(k + 1) * NTOT + c + 8]);
    v.w = pack2(W[(size_t)(k + 8) * NTOT + c + 8], W[(size_t)(k + 9) * NTOT + c + 8]);
    o[u] = v;
}

__global__ void pack_all(const float* __restrict__ x, const float* __restrict__ Wq,
                         const float* __restrict__ Wp,
                         uint4* __restrict__ xr, uint4* __restrict__ wq,
                         uint4* __restrict__ wp)
{
    int blk = blockIdx.x;
    if (blk < 16384) {
        pack_x_body(x, xr, blk * 256 + threadIdx.x);
    } else if (blk < 16768) {
        pack_w_body<1536>(Wq, wq, (blk - 16384) * 256 + threadIdx.x);
    } else {
        pack_w_body<512>(Wp, wp, (blk - 16768) * 256 + threadIdx.x);
    }
}

// Scatter an adjacent-c pair into packed-A layout as one half2 store.
DEVI void store_attn_packed_h2(int m, int c, float v0, float v1) {
    int mt = m >> 7, rr = m & 127;
    int wm = rr >> 5, mf = (rr >> 4) & 1, e0 = (rr >> 3) & 1, g = rr & 7;
    int kt = c >> 5, ck = c & 31;
    int kk = (ck >> 4) & 1, e1 = (ck >> 3) & 1, t = (ck >> 1) & 3;
    size_t u = ((size_t)(mt * 16 + kt)) * 512 + wm * 128 + mf * 64 + kk * 32 + g * 4 + t;
    *(__half2*)((__half*)g_attn + (u * 4 + e1 * 2 + e0) * 2) = __floats2half2_rn(v0, v1);
}

// ---------------------------------------------------------------------------
// fp16 GEMM: CTA 128x128, warps 4(M)x2(N), 3-stage cp.async (R8-proven).
// EPI==0: qkv -> canonical fp16 Q/K/V via paired half2 stores.  EPI==1: fp32 out.
// ---------------------------------------------------------------------------
template <int EPI>
__global__ void __launch_bounds__(256, 2) tc_gemm(
    const uint4* __restrict__ Apk, const uint4* __restrict__ Bpk,
    const float* __restrict__ bias, float* __restrict__ out)
{
    extern __shared__ unsigned char sm[];
    const uint32_t smb = smem_u32(sm);
    const int tid = threadIdx.x, lane = tid & 31, wid = tid >> 5;
    const int wm = wid & 3, wn = wid >> 2;
    const int nt = blockIdx.x, mt = blockIdx.y;

    const uint4* Ag = Apk + (size_t)mt * 8192;
    const uint4* Bg = Bpk + (size_t)nt * 8192;

    auto load_tile = [&](int kt, int s) {
        const uint32_t dst = smb + s * 16384;
        const uint4* sa = Ag + kt * 512;
        const uint4* sb = Bg + kt * 512;
        cp16(dst + tid * 16, sa + tid);
        cp16(dst + (tid + 256) * 16, sa + tid + 256);
        cp16(dst + 8192 + tid * 16, sb + tid);
        cp16(dst + 8192 + (tid + 256) * 16, sb + tid + 256);
        cp_commit();
    };

    float acc[2][8][4];
#pragma unroll
    for (int mf = 0; mf < 2; mf++)
#pragma unroll
        for (int nf = 0; nf < 8; nf++)
#pragma unroll
            for (int r = 0; r < 4; r++) acc[mf][nf][r] = 0.f;

    load_tile(0, 0);
    load_tile(1, 1);

    for (int kt = 0; kt < 16; kt++) {
        if (kt < 15) cp_wait<1>(); else cp_wait<0>();
        __syncthreads();
        if (kt + 2 < 16) load_tile(kt + 2, (kt + 2) % 3);

        const uint32_t st = smb + (kt % 3) * 16384;
        const uint32_t aB = st + (wm * 128 + lane) * 16;
        const uint32_t bB = st + 8192 + (wn * 256 + lane) * 16;
#pragma unroll
        for (int kk = 0; kk < 2; kk++) {
            uint4 a0 = lds128(aB + kk * 512);
            uint4 a1 = lds128(aB + 1024 + kk * 512);
            uint4 b0 = lds128(bB + kk * 512);
            uint4 b1 = lds128(bB + 1024 + kk * 512);
            uint4 b2 = lds128(bB + 2048 + kk * 512);
            uint4 b3 = lds128(bB + 3072 + kk * 512);
            mma16(acc[0][0], a0, b0.x, b0.y);
            mma16(acc[0][1], a0, b0.z, b0.w);
            mma16(acc[0][2], a0, b1.x, b1.y);
            mma16(acc[0][3], a0, b1.z, b1.w);
            mma16(acc[0][4], a0, b2.x, b2.y);
            mma16(acc[0][5], a0, b2.z, b2.w);
            mma16(acc[0][6], a0, b3.x, b3.y);
            mma16(acc[0][7], a0, b3.z, b3.w);
            mma16(acc[1][0], a1, b0.x, b0.y);
            mma16(acc[1][1], a1, b0.z, b0.w);
            mma16(acc[1][2], a1, b1.x, b1.y);
            mma16(acc[1][3], a1, b1.z, b1.w);
            mma16(acc[1][4], a1, b2.x, b2.y);
            mma16(acc[1][5], a1, b2.z, b2.w);
            mma16(acc[1][6], a1, b3.x, b3.y);
            mma16(acc[1][7], a1, b3.z, b3.w);
        }
    }

#pragma unroll
    for (int mf = 0; mf < 2; mf++)
#pragma unroll
        for (int nf = 0; nf < 8; nf++)
#pragma unroll
            for (int rp = 0; rp < 2; rp++) {
                int row = mt * 128 + wm * 32 + mf * 16 + (lane >> 2) + rp * 8;
                int cc = nt * 128 + wn * 64 + nf * 8 + (lane & 3) * 2;
                float v0 = acc[mf][nf][rp * 2] + bias[cc];
                float v1 = acc[mf][nf][rp * 2 + 1] + bias[cc + 1];
                if (EPI == 0) {
                    int b = row >> 13, n = row & 8191;
                    int blk = n >> 5, s = n & 31;
                    int bs = b * 32 + s;
                    int hh = cc / 192, rr = cc - hh * 192;
                    int kind = rr >> 6, c = hh * 64 + (rr & 63);
                    __half2 hv = __floats2half2_rn(v0, v1);
                    __half* dp = (kind == 0) ? g_qh : (kind == 1) ? g_kh : g_vh;
                    *(__half2*)(dp + ((size_t)(bs * 256 + blk)) * 512 + c) = hv;
                } else {
                    float* db = out + (size_t)row * 512 + cc;
                    db[0] = v0;
                    db[1] = v1;
                }
            }
}

// ---------------------------------------------------------------------------
// Banded attention body, fp16 mma + ldmatrix + register-resident softmax.
// 8 warps: 2(M) x 4(N). SMEM: region A time-shared (phase-1 Q/K tiles ->
// phase-2 V tiles), persistent fp16 P above it, 2x1KB reduction partials.
// ---------------------------------------------------------------------------
template <int W>
DEVI void attn_body(int bs, int qt, const uint32_t smb, unsigned char* smraw)
{
    constexpr int NF = W / 32;
    constexpr int SSTH = W + 8;
    constexpr int QS_SZ = 64 * 80;
    constexpr int QK_ST = (64 + W) * 80;
    constexpr int V_ST = 32 * 528;
    constexpr int REGA = 61440;           // max(3*QK_ST(192), 3*V_ST)
    constexpr int OFF_P = REGA;
    constexpr int OFF_R = OFF_P + 25600;  // pmax [64][4] floats
    constexpr int OFF_S = OFF_R + 1024;   // psum [64][4] floats

    const int tid = threadIdx.x, lane = tid & 31, wid = tid >> 5;
    const int g = lane >> 2, t = lane & 3;
    const int wm = wid & 1, wn = wid >> 1;
    const int i0 = qt * 64;
    const int jlo = (i0 >= 64) ? (i0 - 64) : 0;

    const __half* Qg = g_qh + (size_t)(bs * 256 + i0) * 512;
    const __half* Kg = g_kh + (size_t)(bs * 256 + jlo) * 512;
    const __half* Vg = g_vh + (size_t)(bs * 256 + jlo) * 512;

    // ---------------- phase 1: S = Q K^T ----------------
    auto ldqk = [&](int kt, int s) {
        const int k0 = kt * 32;
        const uint32_t qd = smb + s * QK_ST;
        const uint32_t kd = qd + QS_SZ;
        {
            int row = tid >> 2, hc = (tid & 3) * 8;
            cp16(qd + row * 80 + hc * 2, Qg + (size_t)row * 512 + k0 + hc);
        }
#pragma unroll
        for (int i = 0; i < W / 64; i++) {
            int u = tid + i * 256;
            int row = u >> 2, hc = (u & 3) * 8;
            cp16(kd + row * 80 + hc * 2, Kg + (size_t)row * 512 + k0 + hc);
        }
        cp_commit();
    };
    auto ldv = [&](int half, int jt, int st) {
        const uint32_t vd = smb + st * V_ST;
#pragma unroll
        for (int i = 0; i < 4; i++) {
            int u = tid + i * 256;
            int row = u >> 5, ch = u & 31;
            cp16(vd + row * 528 + ch * 16,
                 Vg + (size_t)(jt * 32 + row) * 512 + half * 256 + ch * 8);
        }
        cp_commit();
    };

    float acc[2][NF][4];
#pragma unroll
    for (int mf = 0; mf < 2; mf++)
#pragma unroll
        for (int nf = 0; nf < NF; nf++)
#pragma unroll
            for (int r = 0; r < 4; r++) acc[mf][nf][r] = 0.f;

    ldqk(0, 0);
    ldqk(1, 1);

    for (int kt = 0; kt < 16; kt++) {
        if (kt < 15) cp_wait<1>(); else cp_wait<0>();
        __syncthreads();
        if (kt + 2 < 16) ldqk(kt + 2, (kt + 2) % 3);

        const uint32_t qb = smb + (kt % 3) * QK_ST;
        const uint32_t kb = qb + QS_SZ;
#pragma unroll
        for (int kk = 0; kk < 2; kk++) {
            uint4 a[2];
#pragma unroll
            for (int mf = 0; mf < 2; mf++)
                ldsm4(a[mf], qb + (wm * 32 + mf * 16 + (lane & 15)) * 80 +
                              kk * 32 + (lane >> 4) * 16);
#pragma unroll
            for (int np = 0; np < NF / 2; np++) {
                uint4 bm;
                ldsm4(bm, kb + (wn * (W / 4) + (np * 2 + (lane >> 4)) * 8 + (lane & 7)) * 80 +
                           kk * 32 + ((lane >> 3) & 1) * 16);
                mma16(acc[0][np * 2], a[0], bm.x, bm.y);
                mma16(acc[1][np * 2], a[1], bm.x, bm.y);
                mma16(acc[0][np * 2 + 1], a[0], bm.z, bm.w);
                mma16(acc[1][np * 2 + 1], a[1], bm.z, bm.w);
            }
        }
    }
    __syncthreads();   // tiles dead; region A free for V

    // overlap: prefetch first two V tiles of half 0 under the softmax
    ldv(0, 0, 0);
    ldv(0, 1, 1);

    // ---------------- register softmax ----------------
    float* pmax = (float*)(smraw + OFF_R);
    float* psum = (float*)(smraw + OFF_S);

    float mx[2][2];
#pragma unroll
    for (int mf = 0; mf < 2; mf++)
#pragma unroll
        for (int e0 = 0; e0 < 2; e0++) mx[mf][e0] = -3.4e38f;
#pragma unroll
    for (int mf = 0; mf < 2; mf++)
#pragma unroll
        for (int nf = 0; nf < NF; nf++)
#pragma unroll
            for (int r = 0; r < 4; r++) {
                int row = wm * 32 + mf * 16 + g + ((r & 2) ? 8 : 0);
                int jl = wn * (W / 4) + nf * 8 + t * 2 + (r & 1);
                int i = i0 + row, j = jlo + jl;
                float v = acc[mf][nf][r] * 0.125f;
                if (j < i - 64 || j > i + 64) v = -1.0e30f;
                acc[mf][nf][r] = v;
                mx[mf][r >> 1] = fmaxf(mx[mf][r >> 1], v);
            }
#pragma unroll
    for (int mf = 0; mf < 2; mf++)
#pragma unroll
        for (int e0 = 0; e0 < 2; e0++) {
            mx[mf][e0] = fmaxf(mx[mf][e0], __shfl_xor_sync(0xffffffffu, mx[mf][e0], 1));
            mx[mf][e0] = fmaxf(mx[mf][e0], __shfl_xor_sync(0xffffffffu, mx[mf][e0], 2));
        }
    if (t == 0) {
#pragma unroll
        for (int mf = 0; mf < 2; mf++)
#pragma unroll
            for (int e0 = 0; e0 < 2; e0++)
                pmax[(wm * 32 + mf * 16 + g + 8 * e0) * 4 + wn] = mx[mf][e0];
    }
    __syncthreads();

    float sm[2][2];
#pragma unroll
    for (int mf = 0; mf < 2; mf++)
#pragma unroll
        for (int e0 = 0; e0 < 2; e0++) {
            float4 p4 = *(float4*)&pmax[(wm * 32 + mf * 16 + g + 8 * e0) * 4];
            float rmx = fmaxf(fmaxf(p4.x, p4.y), fmaxf(p4.z, p4.w));
            float s = 0.f;
#pragma unroll
            for (int nf = 0; nf < NF; nf++)
#pragma unroll
                for (int e1 = 0; e1 < 2; e1++) {
                    float e = __expf(acc[mf][nf][2 * e0 + e1] - rmx);
                    acc[mf][nf][2 * e0 + e1] = e;
                    s += e;
                }
            sm[mf][e0] = s;
        }
#pragma unroll
    for (int mf = 0; mf < 2; mf++)
#pragma unroll
        for (int e0 = 0; e0 < 2; e0++) {
            sm[mf][e0] += __shfl_xor_sync(0xffffffffu, sm[mf][e0], 1);
            sm[mf][e0] += __shfl_xor_sync(0xffffffffu, sm[mf][e0], 2);
        }
    if (t == 0) {
#pragma unroll
        for (int mf = 0; mf < 2; mf++)
#pragma unroll
            for (int e0 = 0; e0 < 2; e0++)
                psum[(wm * 32 + mf * 16 + g + 8 * e0) * 4 + wn] = sm[mf][e0];
    }
    __syncthreads();

    __half* pp = (__half*)(smraw + OFF_P);
#pragma unroll
    for (int mf = 0; mf < 2; mf++)
#pragma unroll
        for (int e0 = 0; e0 < 2; e0++) {
            int row = wm * 32 + mf * 16 + g + 8 * e0;
            float4 s4 = *(float4*)&psum[row * 4];
            float inv = 1.0f / (s4.x + s4.y + s4.z + s4.w);
#pragma unroll
            for (int nf = 0; nf < NF; nf++) {
                int jl = wn * (W / 4) + nf * 8 + t * 2;
                *(__half2*)(pp + row * SSTH + jl) =
                    __floats2half2_rn(acc[mf][nf][2 * e0] * inv,
                                      acc[mf][nf][2 * e0 + 1] * inv);
            }
        }
    __syncthreads();   // P visible

    // ---------------- phase 2: O = P V ----------------
    const int b = bs >> 5, s = bs & 31;

    for (int half = 0; half < 2; half++) {
        if (half == 1) {
            __syncthreads();   // half-0 readers done with V slots
            ldv(1, 0, 0);
            ldv(1, 1, 1);
        }

        float acc2[2][8][4];
#pragma unroll
        for (int mf = 0; mf < 2; mf++)
#pragma unroll
            for (int nf = 0; nf < 8; nf++)
#pragma unroll
                for (int r = 0; r < 4; r++) acc2[mf][nf][r] = 0.f;

        for (int jt = 0; jt < NF; jt++) {
            if (jt < NF - 1) cp_wait<1>(); else cp_wait<0>();
            __syncthreads();
            if (jt + 2 < NF) ldv(half, jt + 2, (jt + 2) % 3);

            const uint32_t vb = smb + (jt % 3) * V_ST;
#pragma unroll
            for (int kk = 0; kk < 2; kk++) {
                uint4 a[2];
#pragma unroll
                for (int mf = 0; mf < 2; mf++)
                    ldsm4(a[mf], smb + OFF_P + (wm * 32 + mf * 16 + (lane & 15)) * (SSTH * 2) +
                                  (jt * 32 + kk * 16 + (lane >> 4) * 8) * 2);
#pragma unroll
                for (int np = 0; np < 4; np++) {
                    uint4 bm;
                    ldsm4t(bm, vb + (kk * 16 + ((lane >> 3) & 1) * 8 + (lane & 7)) * 528 +
                                (wn * 64 + (np * 2 + (lane >> 4)) * 8) * 2);
                    mma16(acc2[0][np * 2], a[0], bm.x, bm.y);
                    mma16(acc2[1][np * 2], a[1], bm.x, bm.y);
                    mma16(acc2[0][np * 2 + 1], a[0], bm.z, bm.w);
                    mma16(acc2[1][np * 2 + 1], a[1], bm.z, bm.w);
                }
            }
        }

#pragma unroll
        for (int mf = 0; mf < 2; mf++)
#pragma unroll
            for (int nf = 0; nf < 8; nf++)
#pragma unroll
                for (int rp = 0; rp < 2; rp++) {
                    int row = wm * 32 + mf * 16 + g + rp * 8;
                    int c = half * 256 + wn * 64 + nf * 8 + t * 2;
                    int m = b * 8192 + (i0 + row) * 32 + s;
                    store_attn_packed_h2(m, c, acc2[mf][nf][rp * 2], acc2[mf][nf][rp * 2 + 1]);
                }
    }
}

// Merged attention, INTERLEAVED: even idx -> W=192 (heavy), odd -> W=128.
// Every wave carries the average load; 2 co-resident CTAs/SM mix phases.
__global__ void __launch_bounds__(256, 2) attn_all()
{
    extern __shared__ unsigned char smraw[];
    const uint32_t smb = smem_u32(smraw);
    const int idx = blockIdx.x;
    const int r = idx >> 1;
    if ((idx & 1) == 0) {
        const int bs = r >> 1;
        const int qt = 1 + (r & 1);
        attn_body<192>(bs, qt, smb, smraw);
    } else {
        const int bs = r >> 1;
        const int qt = (r & 1) ? 3 : 0;
        attn_body<128>(bs, qt, smb, smraw);
    }
}

// ---------------------------------------------------------------------------
extern "C" void kernel_launch(void* const* d_in, const int* in_sizes, int n_in,
                              void* d_out, int out_size)
{
    const float* x  = (const float*)d_in[0];
    const float* Wq = (const float*)d_in[1];
    const float* bq = (const float*)d_in[2];
    const float* Wp = (const float*)d_in[3];
    const float* bp = (const float*)d_in[4];
    float* out = (float*)d_out;

    void *pxr, *pwq, *pwp, *pattn;
    cudaGetSymbolAddress(&pxr, g_xr);
    cudaGetSymbolAddress(&pwq, g_wq);
    cudaGetSymbolAddress(&pwp, g_wp);
    cudaGetSymbolAddress(&pattn, g_attn);

    const int smG = 3 * 16384;             // 49152 (3-stage, R8-proven)
    const int smA = 61440 + 25600 + 2048;  // REGA + P + pmax/psum = 89088 -> 2 CTAs/SM

    cudaFuncSetAttribute(tc_gemm<0>, cudaFuncAttributeMaxDynamicSharedMemorySize, smG);
    cudaFuncSetAttribute(tc_gemm<1>, cudaFuncAttributeMaxDynamicSharedMemorySize, smG);
    cudaFuncSetAttribute(attn_all, cudaFuncAttributeMaxDynamicSharedMemorySize, smA);

    // 0) fused pack + fp16-round of all operands (one launch)
    pack_all<<<16896, 256>>>(x, Wq, Wp, (uint4*)pxr, (uint4*)pwq, (uint4*)pwp);

    // 1) QKV projection (fp16 mma) -> canonical fp16 Q/K/V (half2 stores)
    tc_gemm<0><<<dim3(12, 512), 256, smG>>>((const uint4*)pxr, (const uint4*)pwq, bq, nullptr);

    // 2) merged banded attention (interleaved heavy/light CTAs)
    attn_all<<<1024, 256, smA>>>();

    // 3) output projection (fp16 mma)
    tc_gemm<1><<<dim3(4, 512), 256, smG>>>((const uint4*)pattn, (const uint4*)pwp, bp, out);
}